// round 4
// baseline (speedup 1.0000x reference)
#include <cuda_runtime.h>

// CapsuleLayer dynamic routing, fp32.
//   inputs: (64, 512, 128) fp32
//   W:      (512, 16, 128, 32) fp32
//   num_routing = 3 (fixed by setup_inputs)
//   out:    (64, 16, 32) fp32
//
// Plan:
//   K1 uhat_kernel : u_hat[b,i,j,d] = sum_k inputs[b,i,k] * W[i,j,k,d]
//                    one block per i; A held in SMEM duplicated as (a,a) pairs so the
//                    outer product maps onto packed fma.rn.f32x2 (FFMA2) with no MOVs.
//   K2 s_squash    : s[b,j,d] = sum_i c[b,i,j]*u_hat ; v = squash(s)
//   K3 agree       : b[b,i,j] (+)= dot_d(v[b,j,:], u_hat[b,i,j,:]) ; c = softmax_j(b)
//   Sequence: K1, K2(uniform), K3(first), K2, K3, K2(final -> d_out)

#define B_    64
#define ICAPS 512
#define IDIM  128
#define NCAPS 16
#define ODIM  32

// Scratch (allocation-free rule: __device__ globals)
__device__ float g_uhat[(size_t)B_ * ICAPS * NCAPS * ODIM];  // 67 MB
__device__ float g_b[(size_t)B_ * ICAPS * NCAPS];
__device__ float g_c[(size_t)B_ * ICAPS * NCAPS];
__device__ float g_v[(size_t)B_ * NCAPS * ODIM];

__device__ __forceinline__ void fma2(unsigned long long& c,
                                     unsigned long long a,
                                     unsigned long long b) {
    asm("fma.rn.f32x2 %0, %1, %2, %0;" : "+l"(c) : "l"(a), "l"(b));
}

// ---------------------------------------------------------------------------
// K1: u_hat GEMM. grid = 512 (one block per input capsule i), 256 threads.
// Dynamic SMEM 96KB: Adup[128][128] (A duplicated along b) + Ws[2][128][32].
// Thread tile: 4 b-rows x 4 d-cols; 128 threads per j, 2 j's concurrently.
// ---------------------------------------------------------------------------
__global__ void __launch_bounds__(256, 2)
uhat_kernel(const float* __restrict__ x, const float* __restrict__ W) {
    extern __shared__ float smem[];
    float* Adup = smem;                 // [k][2b], row stride 128 floats
    float* Wsh  = smem + 128 * 128;     // [jj][k][d], 2*128*32

    const int i   = blockIdx.x;
    const int tid = threadIdx.x;

    // Load A = inputs[:, i, :] duplicated: Adup[k][2b] = Adup[k][2b+1] = x[b,i,k]
    // Lanes vary b (conflict-free STS.64); global reads are strided but tiny (32KB/block).
    for (int idx = tid; idx < 64 * 32; idx += 256) {
        int b  = idx & 63;
        int kq = idx >> 6;  // float4 index along k
        float4 v = *reinterpret_cast<const float4*>(
            x + ((size_t)b * ICAPS + i) * IDIM + kq * 4);
        int k = kq * 4;
        *reinterpret_cast<float2*>(Adup + (k + 0) * 128 + 2 * b) = make_float2(v.x, v.x);
        *reinterpret_cast<float2*>(Adup + (k + 1) * 128 + 2 * b) = make_float2(v.y, v.y);
        *reinterpret_cast<float2*>(Adup + (k + 2) * 128 + 2 * b) = make_float2(v.z, v.z);
        *reinterpret_cast<float2*>(Adup + (k + 3) * 128 + 2 * b) = make_float2(v.w, v.w);
    }

    const int jj = tid >> 7;   // which of 2 concurrent j's
    const int t  = tid & 127;
    const int bt = t >> 3;     // 0..15 -> b0 = 4*bt
    const int dt = t & 7;      // 0..7  -> d0 = 4*dt

    const float* Wi = W + (size_t)i * NCAPS * IDIM * ODIM;

    for (int jp = 0; jp < 8; ++jp) {
        __syncthreads();  // previous Ws consumers done (also covers Adup stores at jp=0)
        // Load W tiles for j = 2*jp, 2*jp+1 (each tile is 4096 contiguous floats)
        {
            const float4* src = reinterpret_cast<const float4*>(
                Wi + (size_t)jp * 2 * IDIM * ODIM);
            float4* dst = reinterpret_cast<float4*>(Wsh);
            #pragma unroll
            for (int l = tid; l < 2048; l += 256) dst[l] = src[l];
        }
        __syncthreads();

        unsigned long long c2[4][2];
        #pragma unroll
        for (int q = 0; q < 4; ++q) { c2[q][0] = 0ull; c2[q][1] = 0ull; }

        const float* wbase = Wsh + jj * 128 * 32 + dt * 4;
        const float* abase = Adup + bt * 8;

        #pragma unroll 8
        for (int k = 0; k < 128; ++k) {
            ulonglong2 w   = *reinterpret_cast<const ulonglong2*>(wbase + k * 32);
            ulonglong2 a01 = *reinterpret_cast<const ulonglong2*>(abase + k * 128);
            ulonglong2 a23 = *reinterpret_cast<const ulonglong2*>(abase + k * 128 + 4);
            fma2(c2[0][0], a01.x, w.x); fma2(c2[0][1], a01.x, w.y);
            fma2(c2[1][0], a01.y, w.x); fma2(c2[1][1], a01.y, w.y);
            fma2(c2[2][0], a23.x, w.x); fma2(c2[2][1], a23.x, w.y);
            fma2(c2[3][0], a23.y, w.x); fma2(c2[3][1], a23.y, w.y);
        }

        const int j  = jp * 2 + jj;
        const int b0 = bt * 4;
        const int d0 = dt * 4;
        #pragma unroll
        for (int bb = 0; bb < 4; ++bb) {
            union { unsigned long long u; float2 f; } u0, u1;
            u0.u = c2[bb][0];
            u1.u = c2[bb][1];
            float4 o = make_float4(u0.f.x, u0.f.y, u1.f.x, u1.f.y);
            *reinterpret_cast<float4*>(
                g_uhat + ((((size_t)(b0 + bb) * ICAPS + i) * NCAPS + j) * ODIM + d0)) = o;
        }
    }
}

// ---------------------------------------------------------------------------
// K2: s = sum_i c * u_hat, then squash. grid = (64, 16), 256 threads.
// uniform=1 -> c = 1/16 (softmax of zeros). final=1 -> write d_out, else g_v.
// ---------------------------------------------------------------------------
__global__ void s_squash_kernel(float* __restrict__ out, int uniform, int final_iter) {
    const int b = blockIdx.x;
    const int j = blockIdx.y;
    const int d = threadIdx.x & 31;
    const int g = threadIdx.x >> 5;  // 8 i-groups

    const float* U = g_uhat + (((size_t)b * ICAPS) * NCAPS + j) * ODIM + d;
    const float* C = g_c + (size_t)b * ICAPS * NCAPS + j;

    float acc = 0.f;
    #pragma unroll 4
    for (int i = g; i < ICAPS; i += 8) {
        float u  = U[(size_t)i * NCAPS * ODIM];
        float cc = uniform ? 0.0625f : C[(size_t)i * NCAPS];
        acc = fmaf(cc, u, acc);
    }

    __shared__ float sm[8][32];
    sm[g][d] = acc;
    __syncthreads();

    if (threadIdx.x < 32) {
        float s = 0.f;
        #pragma unroll
        for (int g2 = 0; g2 < 8; ++g2) s += sm[g2][d];
        float ss = s * s;
        #pragma unroll
        for (int o = 16; o; o >>= 1) ss += __shfl_xor_sync(0xffffffffu, ss, o);
        // squash: scale = ss/(1+ss)/sqrt(ss+1e-7)
        float scale = ss / (1.f + ss) * rsqrtf(ss + 1e-7f);
        float* dst = final_iter ? out : g_v;
        dst[((size_t)b * NCAPS + j) * ODIM + d] = scale * s;
    }
}

// ---------------------------------------------------------------------------
// K3: agreement + softmax. One warp per (b,i). grid = 4096 x 256 (8 warps/blk).
// addPrev=0 treats previous b as 0 (first routing update).
// ---------------------------------------------------------------------------
__global__ void agree_kernel(int addPrev) {
    const int gw   = (blockIdx.x * blockDim.x + threadIdx.x) >> 5;  // b*512+i
    const int lane = threadIdx.x & 31;
    if (gw >= B_ * ICAPS) return;
    const int b = gw >> 9;

    const float* U = g_uhat + (size_t)gw * NCAPS * ODIM;
    const float* V = g_v + (size_t)b * NCAPS * ODIM;

    float bj[NCAPS];
    #pragma unroll
    for (int j = 0; j < NCAPS; ++j) {
        float p = U[j * ODIM + lane] * V[j * ODIM + lane];
        #pragma unroll
        for (int o = 16; o; o >>= 1) p += __shfl_xor_sync(0xffffffffu, p, o);
        bj[j] = p;  // broadcast to all lanes by xor-reduce
    }

    float* Bp = g_b + (size_t)gw * NCAPS;
    if (addPrev) {
        #pragma unroll
        for (int j = 0; j < NCAPS; ++j) bj[j] += Bp[j];
    }

    // softmax over j (replicated across lanes; 16 values)
    float m = bj[0];
    #pragma unroll
    for (int j = 1; j < NCAPS; ++j) m = fmaxf(m, bj[j]);
    float ej[NCAPS];
    float sum = 0.f;
    #pragma unroll
    for (int j = 0; j < NCAPS; ++j) { ej[j] = expf(bj[j] - m); sum += ej[j]; }
    float inv = 1.f / sum;

    float bsel = 0.f, csel = 0.f;
    #pragma unroll
    for (int j = 0; j < NCAPS; ++j)
        if (lane == j) { bsel = bj[j]; csel = ej[j] * inv; }
    if (lane < NCAPS) {
        Bp[lane] = bsel;
        g_c[(size_t)gw * NCAPS + lane] = csel;
    }
}

// ---------------------------------------------------------------------------
extern "C" void kernel_launch(void* const* d_in, const int* in_sizes, int n_in,
                              void* d_out, int out_size) {
    const float* x = (const float*)d_in[0];
    const float* W = (const float*)d_in[1];
    float* out = (float*)d_out;

    cudaFuncSetAttribute(uhat_kernel,
                         cudaFuncAttributeMaxDynamicSharedMemorySize, 96 * 1024);

    // u_hat
    uhat_kernel<<<ICAPS, 256, 96 * 1024>>>(x, W);

    dim3 gs(B_, NCAPS);
    // r = 0: c uniform
    s_squash_kernel<<<gs, 256>>>(out, /*uniform=*/1, /*final=*/0);
    agree_kernel<<<4096, 256>>>(/*addPrev=*/0);
    // r = 1
    s_squash_kernel<<<gs, 256>>>(out, 0, 0);
    agree_kernel<<<4096, 256>>>(/*addPrev=*/1);
    // r = 2 (final)
    s_squash_kernel<<<gs, 256>>>(out, 0, /*final=*/1);
}

// round 8
// speedup vs baseline: 2.0818x; 2.0818x over previous
#include <cuda_runtime.h>
#include <cuda_bf16.h>
#include <cstdint>

// CapsuleLayer dynamic routing.
//   inputs: (64, 512, 128) fp32 ; W: (512, 16, 128, 32) fp32 ; num_routing=3
//   out: (64, 16, 32) fp32
//
// K1 uhat_mma   : u_hat via mma.sync m16n8k16 bf16 split-precision
//                 (Ah*Bh + Ah*Bl + Al*Bh, fp32 accum). A = x, B = W (fp32 in
//                 SMEM, converted to bf16 hi/lo on the fly -- no transpose).
// K2 s_uniform  : r=0 weighted sum (c = 1/16) + squash -> v
// K3 fused_route: agreement dot + bias + softmax + weighted-sum partials
// K4 squash_reduce: reduce partials + squash -> v or final out

#define B_    64
#define ICAPS 512
#define IDIM  128
#define NCAPS 16
#define ODIM  32

__device__ float g_uhat[(size_t)B_ * ICAPS * NCAPS * ODIM];  // 67 MB
__device__ float g_b[(size_t)B_ * ICAPS * NCAPS];
__device__ float g_v[(size_t)B_ * NCAPS * ODIM];
__device__ float g_part[(size_t)8 * B_ * NCAPS * ODIM];

// ---------------- helpers ----------------
// packed bf16x2 = truncated high halves of (v0, v1): exact, 1 instr
__device__ __forceinline__ uint32_t prmt_hi(float v0, float v1) {
    uint32_t r;
    asm("prmt.b32 %0, %1, %2, 0x7632;"
        : "=r"(r) : "r"(__float_as_uint(v0)), "r"(__float_as_uint(v1)));
    return r;
}
// packed bf16x2 of residuals (v - trunc_bf16(v)); subtraction is exact
__device__ __forceinline__ uint32_t lo_pack(float v0, float v1) {
    float h0 = __uint_as_float(__float_as_uint(v0) & 0xFFFF0000u);
    float h1 = __uint_as_float(__float_as_uint(v1) & 0xFFFF0000u);
    float l0 = v0 - h0, l1 = v1 - h1;
    uint32_t r;
    asm("cvt.rn.bf16x2.f32 %0, %1, %2;" : "=r"(r) : "f"(l1), "f"(l0));
    return r;
}
__device__ __forceinline__ void mma16816(float* c, const uint32_t* a,
                                         uint32_t b0, uint32_t b1) {
    asm volatile(
        "mma.sync.aligned.m16n8k16.row.col.f32.bf16.bf16.f32 "
        "{%0,%1,%2,%3}, {%4,%5,%6,%7}, {%8,%9}, {%0,%1,%2,%3};"
        : "+f"(c[0]), "+f"(c[1]), "+f"(c[2]), "+f"(c[3])
        : "r"(a[0]), "r"(a[1]), "r"(a[2]), "r"(a[3]), "r"(b0), "r"(b1));
}

#define XH_STRIDE 136   // halves per row (64 rows of x), conflict-free frags
#define W_STRIDE  36    // floats per row (128 k-rows of W), conflict-free
#define OFF_W     (64 * XH_STRIDE * 2 * 2)                  // 34816 B
#define SMEM_BYTES (OFF_W + 128 * W_STRIDE * 4)             // 53248 B

// ---------------------------------------------------------------------------
// K1: one block per input capsule i. 8 warps: warp = (m-tile 0..3, d-half 0..1).
// M=64 (b), N=32 per j (d), K=128. A-frags (x hi/lo) hoisted in 64 regs.
// ---------------------------------------------------------------------------
__global__ void __launch_bounds__(256, 2)
uhat_mma(const float* __restrict__ x, const float* __restrict__ W) {
    extern __shared__ char sm[];
    uint16_t* xh = reinterpret_cast<uint16_t*>(sm);
    uint16_t* xl = xh + 64 * XH_STRIDE;
    float* wraw  = reinterpret_cast<float*>(sm + OFF_W);

    const int i = blockIdx.x, tid = threadIdx.x;
    const int wid = tid >> 5, lane = tid & 31;

    // stage x[:, i, :] as bf16 hi/lo (rows b, k contiguous)
    for (int q = tid; q < 2048; q += 256) {
        int b = q >> 5, k4 = q & 31;
        float4 v = __ldcs(reinterpret_cast<const float4*>(
                              x + ((size_t)b * ICAPS + i) * IDIM) + k4);
        uint32_t h0 = prmt_hi(v.x, v.y), h1 = prmt_hi(v.z, v.w);
        uint32_t l0 = lo_pack(v.x, v.y), l1 = lo_pack(v.z, v.w);
        *reinterpret_cast<uint2*>(xh + b * XH_STRIDE + k4 * 4) = make_uint2(h0, h1);
        *reinterpret_cast<uint2*>(xl + b * XH_STRIDE + k4 * 4) = make_uint2(l0, l1);
    }
    __syncthreads();

    // hoist A-frags: warp's m-tile, all 8 k-steps, hi+lo (64 regs)
    const int m0 = (wid & 3) * 16;
    const int nh = wid >> 2;
    uint32_t A[8][2][4];
    {
        const int r0 = m0 + (lane >> 2);
        const int cb = (lane & 3) * 2;
        #pragma unroll
        for (int ks = 0; ks < 8; ++ks) {
            int c0 = ks * 16 + cb;
            A[ks][0][0] = *reinterpret_cast<const uint32_t*>(xh + r0 * XH_STRIDE + c0);
            A[ks][0][1] = *reinterpret_cast<const uint32_t*>(xh + (r0 + 8) * XH_STRIDE + c0);
            A[ks][0][2] = *reinterpret_cast<const uint32_t*>(xh + r0 * XH_STRIDE + c0 + 8);
            A[ks][0][3] = *reinterpret_cast<const uint32_t*>(xh + (r0 + 8) * XH_STRIDE + c0 + 8);
            A[ks][1][0] = *reinterpret_cast<const uint32_t*>(xl + r0 * XH_STRIDE + c0);
            A[ks][1][1] = *reinterpret_cast<const uint32_t*>(xl + (r0 + 8) * XH_STRIDE + c0);
            A[ks][1][2] = *reinterpret_cast<const uint32_t*>(xl + r0 * XH_STRIDE + c0 + 8);
            A[ks][1][3] = *reinterpret_cast<const uint32_t*>(xl + (r0 + 8) * XH_STRIDE + c0 + 8);
        }
    }

    const int kq = (lane & 3) * 2;   // B-frag k offset
    const int dq = lane >> 2;        // B-frag d (col) offset

    for (int j = 0; j < NCAPS; ++j) {
        __syncthreads();  // wraw free
        // stage W[i,j,:,:] raw fp32 as [k][d], stride 36 (conflict-free)
        const float4* wsrc = reinterpret_cast<const float4*>(
            W + ((size_t)i * NCAPS + j) * IDIM * ODIM);
        for (int q = tid; q < 1024; q += 256) {
            float4 v = __ldcs(wsrc + q);
            int k = q >> 3, dcol = (q & 7) << 2;
            *reinterpret_cast<float4*>(wraw + k * W_STRIDE + dcol) = v;
        }
        __syncthreads();

        float c[2][4] = {{0.f, 0.f, 0.f, 0.f}, {0.f, 0.f, 0.f, 0.f}};
        #pragma unroll
        for (int ks = 0; ks < 8; ++ks) {
            int kr = ks * 16 + kq;
            #pragma unroll
            for (int nt = 0; nt < 2; ++nt) {
                int d = nh * 16 + nt * 8 + dq;
                float v00 = wraw[kr * W_STRIDE + d];
                float v01 = wraw[(kr + 1) * W_STRIDE + d];
                float v10 = wraw[(kr + 8) * W_STRIDE + d];
                float v11 = wraw[(kr + 9) * W_STRIDE + d];
                uint32_t bh0 = prmt_hi(v00, v01), bh1 = prmt_hi(v10, v11);
                uint32_t bl0 = lo_pack(v00, v01), bl1 = lo_pack(v10, v11);
                mma16816(c[nt], A[ks][0], bh0, bh1);  // Ah*Bh
                mma16816(c[nt], A[ks][0], bl0, bl1);  // Ah*Bl
                mma16816(c[nt], A[ks][1], bh0, bh1);  // Al*Bh
            }
        }

        // epilogue: C rows = b, cols = d (contiguous) -> full 32B sectors
        const int brow = m0 + (lane >> 2);
        const int dc0 = nh * 16 + (lane & 3) * 2;
        #pragma unroll
        for (int nt = 0; nt < 2; ++nt) {
            int d = dc0 + nt * 8;
            *reinterpret_cast<float2*>(
                g_uhat + ((((size_t)brow * ICAPS + i) * NCAPS + j) * ODIM + d)) =
                make_float2(c[nt][0], c[nt][1]);
            *reinterpret_cast<float2*>(
                g_uhat + ((((size_t)(brow + 8) * ICAPS + i) * NCAPS + j) * ODIM + d)) =
                make_float2(c[nt][2], c[nt][3]);
        }
    }
}

// ---------------------------------------------------------------------------
// K2: r=0 weighted sum with uniform c=1/16, then squash -> g_v.
// ---------------------------------------------------------------------------
__global__ void s_uniform_kernel() {
    const int b = blockIdx.x, j = blockIdx.y;
    const int d = threadIdx.x & 31, g = threadIdx.x >> 5;
    const float* U = g_uhat + (((size_t)b * ICAPS) * NCAPS + j) * ODIM + d;
    float acc = 0.f;
    #pragma unroll 4
    for (int i = g; i < ICAPS; i += 8) acc += U[(size_t)i * NCAPS * ODIM];
    __shared__ float smr[8][32];
    smr[g][d] = acc;
    __syncthreads();
    if (threadIdx.x < 32) {
        float s = 0.f;
        #pragma unroll
        for (int g2 = 0; g2 < 8; ++g2) s += smr[g2][d];
        s *= 0.0625f;
        float ss = s * s;
        #pragma unroll
        for (int o = 16; o; o >>= 1) ss += __shfl_xor_sync(0xffffffffu, ss, o);
        float scale = ss / (1.f + ss) * rsqrtf(ss + 1e-7f);
        g_v[((size_t)b * NCAPS + j) * ODIM + d] = scale * s;
    }
}

// ---------------------------------------------------------------------------
// K3: fused routing pass. grid (B_, 8 chunks), 256 thr; warp w handles i's.
// ---------------------------------------------------------------------------
__global__ void __launch_bounds__(256)
fused_route(int addPrev) {
    const int b = blockIdx.x, chunk = blockIdx.y;
    const int wid = threadIdx.x >> 5, lane = threadIdx.x & 31;

    float vv[NCAPS];
    #pragma unroll
    for (int j = 0; j < NCAPS; ++j) vv[j] = g_v[((size_t)b * NCAPS + j) * ODIM + lane];

    float sacc[NCAPS];
    #pragma unroll
    for (int j = 0; j < NCAPS; ++j) sacc[j] = 0.f;

    for (int step = 0; step < 8; ++step) {
        const int i = chunk * 64 + step * 8 + wid;
        const float* U = g_uhat + (((size_t)b * ICAPS + i) * NCAPS) * ODIM + lane;
        float u[NCAPS], bj[NCAPS];
        #pragma unroll
        for (int j = 0; j < NCAPS; ++j) u[j] = U[j * ODIM];
        #pragma unroll
        for (int j = 0; j < NCAPS; ++j) {
            float pr = u[j] * vv[j];
            #pragma unroll
            for (int o = 16; o; o >>= 1) pr += __shfl_xor_sync(0xffffffffu, pr, o);
            bj[j] = pr;
        }
        if (addPrev) {
            float bp = (lane < NCAPS) ? g_b[((size_t)b * ICAPS + i) * NCAPS + lane] : 0.f;
            #pragma unroll
            for (int j = 0; j < NCAPS; ++j)
                bj[j] += __shfl_sync(0xffffffffu, bp, j);
        } else {
            float bsel = 0.f;
            #pragma unroll
            for (int j = 0; j < NCAPS; ++j) bsel = (lane == j) ? bj[j] : bsel;
            if (lane < NCAPS) g_b[((size_t)b * ICAPS + i) * NCAPS + lane] = bsel;
        }
        float m = bj[0];
        #pragma unroll
        for (int j = 1; j < NCAPS; ++j) m = fmaxf(m, bj[j]);
        float sum = 0.f, ej[NCAPS];
        #pragma unroll
        for (int j = 0; j < NCAPS; ++j) { ej[j] = __expf(bj[j] - m); sum += ej[j]; }
        float inv = 1.f / sum;
        #pragma unroll
        for (int j = 0; j < NCAPS; ++j) sacc[j] = fmaf(ej[j] * inv, u[j], sacc[j]);
    }

    __shared__ float smr[8][NCAPS][32];
    #pragma unroll
    for (int j = 0; j < NCAPS; ++j) smr[wid][j][lane] = sacc[j];
    __syncthreads();
    for (int pidx = threadIdx.x; pidx < NCAPS * 32; pidx += 256) {
        int j = pidx >> 5, d = pidx & 31;
        float s = 0.f;
        #pragma unroll
        for (int w = 0; w < 8; ++w) s += smr[w][j][d];
        g_part[(((size_t)chunk * B_ + b) * NCAPS + j) * ODIM + d] = s;
    }
}

// ---------------------------------------------------------------------------
// K4: reduce 8 chunks, squash, write g_v or final out.
// ---------------------------------------------------------------------------
__global__ void squash_reduce(float* __restrict__ out, int final_iter) {
    const int b = blockIdx.x, j = blockIdx.y, d = threadIdx.x;
    float s = 0.f;
    #pragma unroll
    for (int c = 0; c < 8; ++c)
        s += g_part[(((size_t)c * B_ + b) * NCAPS + j) * ODIM + d];
    float ss = s * s;
    #pragma unroll
    for (int o = 16; o; o >>= 1) ss += __shfl_xor_sync(0xffffffffu, ss, o);
    float scale = ss / (1.f + ss) * rsqrtf(ss + 1e-7f);
    float* dst = final_iter ? out : g_v;
    dst[((size_t)b * NCAPS + j) * ODIM + d] = scale * s;
}

// ---------------------------------------------------------------------------
extern "C" void kernel_launch(void* const* d_in, const int* in_sizes, int n_in,
                              void* d_out, int out_size) {
    const float* x = (const float*)d_in[0];
    const float* W = (const float*)d_in[1];
    float* out = (float*)d_out;

    cudaFuncSetAttribute(uhat_mma, cudaFuncAttributeMaxDynamicSharedMemorySize,
                         SMEM_BYTES);

    uhat_mma<<<ICAPS, 256, SMEM_BYTES>>>(x, W);

    dim3 gsq(B_, NCAPS);
    s_uniform_kernel<<<gsq, 256>>>();        // r=0 -> v
    fused_route<<<dim3(B_, 8), 256>>>(0);    // r=1: b=dot, softmax, partial s
    squash_reduce<<<gsq, 32>>>(out, 0);      // -> v
    fused_route<<<dim3(B_, 8), 256>>>(1);    // r=2
    squash_reduce<<<gsq, 32>>>(out, 1);      // -> out
}

// round 9
// speedup vs baseline: 2.7704x; 1.3308x over previous
#include <cuda_runtime.h>
#include <cuda_bf16.h>
#include <cstdint>

// CapsuleLayer dynamic routing.
//   inputs: (64, 512, 128) fp32 ; W: (512, 16, 128, 32) fp32 ; num_routing=3
//   out: (64, 16, 32) fp32
//
// K1 uhat_mma      : mma.sync m16n8k16 bf16 split precision (Ah*Bh+Ah*Bl+Al*Bh),
//                    cp.async double-buffered W, 2 output caps per phase.
// K2 s_uniform_part: r=0 weighted sum partials (c = 1/16), contiguous reads.
// K3 fused_route   : agreement dot + bias + softmax + weighted-sum partials.
// K4 squash_reduce : reduce 8 chunk partials + squash -> v or final out.

#define B_    64
#define ICAPS 512
#define IDIM  128
#define NCAPS 16
#define ODIM  32

__device__ float g_uhat[(size_t)B_ * ICAPS * NCAPS * ODIM];  // 67 MB
__device__ float g_b[(size_t)B_ * ICAPS * NCAPS];
__device__ float g_v[(size_t)B_ * NCAPS * ODIM];
__device__ float g_part[(size_t)8 * B_ * NCAPS * ODIM];

// ---------------- helpers ----------------
__device__ __forceinline__ uint32_t smem_u32(const void* p) {
    uint32_t a;
    asm("{ .reg .u64 t; cvta.to.shared.u64 t, %1; cvt.u32.u64 %0, t; }" : "=r"(a) : "l"(p));
    return a;
}
// packed bf16x2 = truncated high halves of (v0, v1): exact, 1 instr
__device__ __forceinline__ uint32_t prmt_hi(float v0, float v1) {
    uint32_t r;
    asm("prmt.b32 %0, %1, %2, 0x7632;"
        : "=r"(r) : "r"(__float_as_uint(v0)), "r"(__float_as_uint(v1)));
    return r;
}
// packed bf16x2 of residuals (v - trunc_bf16(v)); subtraction exact
__device__ __forceinline__ uint32_t lo_pack(float v0, float v1) {
    float h0 = __uint_as_float(__float_as_uint(v0) & 0xFFFF0000u);
    float h1 = __uint_as_float(__float_as_uint(v1) & 0xFFFF0000u);
    float l0 = v0 - h0, l1 = v1 - h1;
    uint32_t r;
    asm("cvt.rn.bf16x2.f32 %0, %1, %2;" : "=r"(r) : "f"(l1), "f"(l0));
    return r;
}
__device__ __forceinline__ void mma16816(float* c, const uint32_t* a,
                                         uint32_t b0, uint32_t b1) {
    asm volatile(
        "mma.sync.aligned.m16n8k16.row.col.f32.bf16.bf16.f32 "
        "{%0,%1,%2,%3}, {%4,%5,%6,%7}, {%8,%9}, {%0,%1,%2,%3};"
        : "+f"(c[0]), "+f"(c[1]), "+f"(c[2]), "+f"(c[3])
        : "r"(a[0]), "r"(a[1]), "r"(a[2]), "r"(a[3]), "r"(b0), "r"(b1));
}
__device__ __forceinline__ void cp16(uint32_t dst, const void* src) {
    asm volatile("cp.async.cg.shared.global [%0], [%1], 16;" :: "r"(dst), "l"(src));
}
#define CP_COMMIT() asm volatile("cp.async.commit_group;" ::: "memory")
#define CP_WAIT(n)  asm volatile("cp.async.wait_group %0;" :: "n"(n) : "memory")

#define XH_STRIDE 136   // halves per x row; conflict-free frag loads
#define W_STRIDE  36    // floats per W k-row; conflict-free frag loads
#define OFF_W      (64 * XH_STRIDE * 2 * 2)                 // 34816 B
#define WBUF_BYTES (2 * 128 * W_STRIDE * 4)                 // 36864 B (2 j)
#define SMEM_BYTES (OFF_W + 2 * WBUF_BYTES)                 // 108544 B

// ---------------------------------------------------------------------------
// K1: one block per input capsule i. 8 warps: warp = (m-tile 0..3, j-of-pair).
// M=64 (b) x N=32 (d) x K=128 per j; 8 phases of 2 j, cp.async double-buffered.
// ---------------------------------------------------------------------------
__global__ void __launch_bounds__(256, 2)
uhat_mma(const float* __restrict__ x, const float* __restrict__ W) {
    extern __shared__ char sm[];
    uint16_t* xh = reinterpret_cast<uint16_t*>(sm);
    uint16_t* xl = xh + 64 * XH_STRIDE;
    float* wbuf0 = reinterpret_cast<float*>(sm + OFF_W);
    float* wbuf1 = reinterpret_cast<float*>(sm + OFF_W + WBUF_BYTES);

    const int i = blockIdx.x, tid = threadIdx.x;
    const int wid = tid >> 5, lane = tid & 31;

    const float* Wi = W + (size_t)i * NCAPS * IDIM * ODIM;

    // issue cp.async for phase jp into dst (2 j = 2048 float4)
    auto issueW = [&](float* dst, int jp) {
        const float4* src = reinterpret_cast<const float4*>(Wi + (size_t)jp * 2 * IDIM * ODIM);
        #pragma unroll
        for (int r = 0; r < 8; ++r) {
            int q = r * 256 + tid;               // q < 2048
            int j2 = q >> 10, rem = q & 1023;    // rem < 1024 float4 per j
            int k = rem >> 3, dcol = (rem & 7) << 2;
            uint32_t da = smem_u32(dst + (j2 * 128 + k) * W_STRIDE + dcol);
            cp16(da, src + q);
        }
        CP_COMMIT();
    };

    // prologue: start W phase 0
    issueW(wbuf0, 0);

    // stage x[:, i, :] as bf16 hi/lo (rows b, k contiguous)
    for (int q = tid; q < 2048; q += 256) {
        int b = q >> 5, k4 = q & 31;
        float4 v = __ldcs(reinterpret_cast<const float4*>(
                              x + ((size_t)b * ICAPS + i) * IDIM) + k4);
        uint32_t h0 = prmt_hi(v.x, v.y), h1 = prmt_hi(v.z, v.w);
        uint32_t l0 = lo_pack(v.x, v.y), l1 = lo_pack(v.z, v.w);
        *reinterpret_cast<uint2*>(xh + b * XH_STRIDE + k4 * 4) = make_uint2(h0, h1);
        *reinterpret_cast<uint2*>(xl + b * XH_STRIDE + k4 * 4) = make_uint2(l0, l1);
    }
    __syncthreads();

    // hoist A-frags: warp's m-tile, all 8 k-steps, hi+lo (64 regs)
    const int m0 = (wid & 3) * 16;
    const int j2w = wid >> 2;
    uint32_t A[8][2][4];
    {
        const int r0 = m0 + (lane >> 2);
        const int cb = (lane & 3) * 2;
        #pragma unroll
        for (int ks = 0; ks < 8; ++ks) {
            int c0 = ks * 16 + cb;
            A[ks][0][0] = *reinterpret_cast<const uint32_t*>(xh + r0 * XH_STRIDE + c0);
            A[ks][0][1] = *reinterpret_cast<const uint32_t*>(xh + (r0 + 8) * XH_STRIDE + c0);
            A[ks][0][2] = *reinterpret_cast<const uint32_t*>(xh + r0 * XH_STRIDE + c0 + 8);
            A[ks][0][3] = *reinterpret_cast<const uint32_t*>(xh + (r0 + 8) * XH_STRIDE + c0 + 8);
            A[ks][1][0] = *reinterpret_cast<const uint32_t*>(xl + r0 * XH_STRIDE + c0);
            A[ks][1][1] = *reinterpret_cast<const uint32_t*>(xl + (r0 + 8) * XH_STRIDE + c0);
            A[ks][1][2] = *reinterpret_cast<const uint32_t*>(xl + r0 * XH_STRIDE + c0 + 8);
            A[ks][1][3] = *reinterpret_cast<const uint32_t*>(xl + (r0 + 8) * XH_STRIDE + c0 + 8);
        }
    }

    const int kq = (lane & 3) * 2;
    const int dq = lane >> 2;

    for (int jp = 0; jp < 8; ++jp) {
        float* wcur = (jp & 1) ? wbuf1 : wbuf0;
        float* wnxt = (jp & 1) ? wbuf0 : wbuf1;
        __syncthreads();                 // buffer we are about to fill is free
        if (jp < 7) { issueW(wnxt, jp + 1); CP_WAIT(1); }
        else        { CP_WAIT(0); }
        __syncthreads();                 // wcur ready for all warps

        const float* wb = wcur + j2w * 128 * W_STRIDE;
        float c[4][4];
        #pragma unroll
        for (int nt = 0; nt < 4; ++nt)
            c[nt][0] = c[nt][1] = c[nt][2] = c[nt][3] = 0.f;

        #pragma unroll
        for (int ks = 0; ks < 8; ++ks) {
            int kr = ks * 16 + kq;
            #pragma unroll
            for (int nt = 0; nt < 4; ++nt) {
                int d = nt * 8 + dq;
                float v00 = wb[kr * W_STRIDE + d];
                float v01 = wb[(kr + 1) * W_STRIDE + d];
                float v10 = wb[(kr + 8) * W_STRIDE + d];
                float v11 = wb[(kr + 9) * W_STRIDE + d];
                uint32_t bh0 = prmt_hi(v00, v01), bh1 = prmt_hi(v10, v11);
                uint32_t bl0 = lo_pack(v00, v01), bl1 = lo_pack(v10, v11);
                mma16816(c[nt], A[ks][0], bh0, bh1);  // Ah*Bh
                mma16816(c[nt], A[ks][0], bl0, bl1);  // Ah*Bl
                mma16816(c[nt], A[ks][1], bh0, bh1);  // Al*Bh
            }
        }

        // epilogue: rows = b, cols = d contiguous -> full sectors
        const int j = jp * 2 + j2w;
        const int brow = m0 + (lane >> 2);
        const int dc0 = (lane & 3) * 2;
        #pragma unroll
        for (int nt = 0; nt < 4; ++nt) {
            int d = nt * 8 + dc0;
            *reinterpret_cast<float2*>(
                g_uhat + ((((size_t)brow * ICAPS + i) * NCAPS + j) * ODIM + d)) =
                make_float2(c[nt][0], c[nt][1]);
            *reinterpret_cast<float2*>(
                g_uhat + ((((size_t)(brow + 8) * ICAPS + i) * NCAPS + j) * ODIM + d)) =
                make_float2(c[nt][2], c[nt][3]);
        }
    }
}

// ---------------------------------------------------------------------------
// K2: r=0 partial sums, c = 1/16. grid (B_, 8), 512 threads (tid = j*32+d).
// Reads u_hat[b,i,:] as fully contiguous 2KB per i.
// ---------------------------------------------------------------------------
__global__ void __launch_bounds__(512)
s_uniform_part() {
    const int b = blockIdx.x, chunk = blockIdx.y, tid = threadIdx.x;
    const float* U = g_uhat + ((size_t)b * ICAPS + chunk * 64) * (NCAPS * ODIM) + tid;
    float acc = 0.f;
    #pragma unroll 4
    for (int ii = 0; ii < 64; ++ii) acc += U[(size_t)ii * NCAPS * ODIM];
    g_part[((size_t)chunk * B_ + b) * (NCAPS * ODIM) + tid] = acc * 0.0625f;
}

// ---------------------------------------------------------------------------
// K3: fused routing pass. grid (B_, 8), 256 thr; warp w handles i's.
// ---------------------------------------------------------------------------
__global__ void __launch_bounds__(256)
fused_route(int addPrev) {
    const int b = blockIdx.x, chunk = blockIdx.y;
    const int wid = threadIdx.x >> 5, lane = threadIdx.x & 31;

    float vv[NCAPS];
    #pragma unroll
    for (int j = 0; j < NCAPS; ++j) vv[j] = g_v[((size_t)b * NCAPS + j) * ODIM + lane];

    float sacc[NCAPS];
    #pragma unroll
    for (int j = 0; j < NCAPS; ++j) sacc[j] = 0.f;

    for (int step = 0; step < 8; ++step) {
        const int i = chunk * 64 + step * 8 + wid;
        const float* U = g_uhat + (((size_t)b * ICAPS + i) * NCAPS) * ODIM + lane;
        float u[NCAPS], bj[NCAPS];
        #pragma unroll
        for (int j = 0; j < NCAPS; ++j) u[j] = U[j * ODIM];
        #pragma unroll
        for (int j = 0; j < NCAPS; ++j) {
            float pr = u[j] * vv[j];
            #pragma unroll
            for (int o = 16; o; o >>= 1) pr += __shfl_xor_sync(0xffffffffu, pr, o);
            bj[j] = pr;
        }
        if (addPrev) {
            float bp = (lane < NCAPS) ? g_b[((size_t)b * ICAPS + i) * NCAPS + lane] : 0.f;
            #pragma unroll
            for (int j = 0; j < NCAPS; ++j)
                bj[j] += __shfl_sync(0xffffffffu, bp, j);
        } else {
            float bsel = 0.f;
            #pragma unroll
            for (int j = 0; j < NCAPS; ++j) bsel = (lane == j) ? bj[j] : bsel;
            if (lane < NCAPS) g_b[((size_t)b * ICAPS + i) * NCAPS + lane] = bsel;
        }
        float m = bj[0];
        #pragma unroll
        for (int j = 1; j < NCAPS; ++j) m = fmaxf(m, bj[j]);
        float sum = 0.f, ej[NCAPS];
        #pragma unroll
        for (int j = 0; j < NCAPS; ++j) { ej[j] = __expf(bj[j] - m); sum += ej[j]; }
        float inv = 1.f / sum;
        #pragma unroll
        for (int j = 0; j < NCAPS; ++j) sacc[j] = fmaf(ej[j] * inv, u[j], sacc[j]);
    }

    __shared__ float smr[8][NCAPS][32];
    #pragma unroll
    for (int j = 0; j < NCAPS; ++j) smr[wid][j][lane] = sacc[j];
    __syncthreads();
    for (int pidx = threadIdx.x; pidx < NCAPS * 32; pidx += 256) {
        int j = pidx >> 5, d = pidx & 31;
        float s = 0.f;
        #pragma unroll
        for (int w = 0; w < 8; ++w) s += smr[w][j][d];
        g_part[(((size_t)chunk * B_ + b) * NCAPS + j) * ODIM + d] = s;
    }
}

// ---------------------------------------------------------------------------
// K4: reduce 8 chunks, squash, write g_v or final out. grid B_, 512 thr.
// warp = j (tid = j*32 + d), coalesced chunk reads.
// ---------------------------------------------------------------------------
__global__ void __launch_bounds__(512)
squash_reduce(float* __restrict__ out, int final_iter) {
    const int b = blockIdx.x, tid = threadIdx.x;
    float s = 0.f;
    #pragma unroll
    for (int c = 0; c < 8; ++c)
        s += g_part[((size_t)c * B_ + b) * (NCAPS * ODIM) + tid];
    float ss = s * s;
    #pragma unroll
    for (int o = 16; o; o >>= 1) ss += __shfl_xor_sync(0xffffffffu, ss, o);
    float scale = ss / (1.f + ss) * rsqrtf(ss + 1e-7f);
    float* dst = final_iter ? out : g_v;
    dst[(size_t)b * (NCAPS * ODIM) + tid] = scale * s;
}

// ---------------------------------------------------------------------------
extern "C" void kernel_launch(void* const* d_in, const int* in_sizes, int n_in,
                              void* d_out, int out_size) {
    const float* x = (const float*)d_in[0];
    const float* W = (const float*)d_in[1];
    float* out = (float*)d_out;

    cudaFuncSetAttribute(uhat_mma, cudaFuncAttributeMaxDynamicSharedMemorySize,
                         SMEM_BYTES);

    uhat_mma<<<ICAPS, 256, SMEM_BYTES>>>(x, W);

    s_uniform_part<<<dim3(B_, 8), 512>>>();   // r=0 partials
    squash_reduce<<<B_, 512>>>(out, 0);       // -> v
    fused_route<<<dim3(B_, 8), 256>>>(0);     // r=1
    squash_reduce<<<B_, 512>>>(out, 0);       // -> v
    fused_route<<<dim3(B_, 8), 256>>>(1);     // r=2
    squash_reduce<<<B_, 512>>>(out, 1);       // -> out
}

// round 10
// speedup vs baseline: 3.2243x; 1.1638x over previous
#include <cuda_runtime.h>
#include <cuda_bf16.h>
#include <cstdint>

// CapsuleLayer dynamic routing.
//   inputs: (64, 512, 128) fp32 ; W: (512, 16, 128, 32) fp32 ; num_routing=3
//   out: (64, 16, 32) fp32
//
// K1 uhat_mma      : mma.sync m16n8k16 bf16 split precision (Ah*Bh+Ah*Bl+Al*Bh).
//                    W pre-converted to bf16 hi/lo in SMEM once per j (XOR-swizzled
//                    transposed layout), register-prefetch double buffering.
// K2 s_uniform_part: r=0 weighted-sum partials (c = 1/16), float4.
// K3 fused_route   : agreement dot + bias + softmax + weighted-sum partials,
//                    8-lane segments (4 i/warp), float4 loads, 3-stage reduce.
// K4 squash_reduce : reduce 8 chunk partials + squash -> v or final out.

#define B_    64
#define ICAPS 512
#define IDIM  128
#define NCAPS 16
#define ODIM  32

__device__ float g_uhat[(size_t)B_ * ICAPS * NCAPS * ODIM];  // 67 MB
__device__ float g_b[(size_t)B_ * ICAPS * NCAPS];
__device__ float g_v[(size_t)B_ * NCAPS * ODIM];
__device__ float g_part[(size_t)8 * B_ * NCAPS * ODIM];

// ---------------- helpers ----------------
// packed bf16x2 = truncated high halves of (v0, v1): exact, 1 instr
__device__ __forceinline__ uint32_t prmt_hi(float v0, float v1) {
    uint32_t r;
    asm("prmt.b32 %0, %1, %2, 0x7632;"
        : "=r"(r) : "r"(__float_as_uint(v0)), "r"(__float_as_uint(v1)));
    return r;
}
// packed bf16x2 of residuals (v - trunc_bf16(v)); subtraction exact
__device__ __forceinline__ uint32_t lo_pack(float v0, float v1) {
    float h0 = __uint_as_float(__float_as_uint(v0) & 0xFFFF0000u);
    float h1 = __uint_as_float(__float_as_uint(v1) & 0xFFFF0000u);
    float l0 = v0 - h0, l1 = v1 - h1;
    uint32_t r;
    asm("cvt.rn.bf16x2.f32 %0, %1, %2;" : "=r"(r) : "f"(l1), "f"(l0));
    return r;
}
__device__ __forceinline__ void mma16816(float* c, const uint32_t* a,
                                         uint32_t b0, uint32_t b1) {
    asm volatile(
        "mma.sync.aligned.m16n8k16.row.col.f32.bf16.bf16.f32 "
        "{%0,%1,%2,%3}, {%4,%5,%6,%7}, {%8,%9}, {%0,%1,%2,%3};"
        : "+f"(c[0]), "+f"(c[1]), "+f"(c[2]), "+f"(c[3])
        : "r"(a[0]), "r"(a[1]), "r"(a[2]), "r"(a[3]), "r"(b0), "r"(b1));
}

#define XH_STRIDE 136   // halves per x row; conflict-free frag loads
// Converted-W word offset: h (hi=0/lo=1), kb (k>>6), d row (0..31), w = pair idx
// in kb (0..31). Pitch 36 words; XOR swizzle keeps BOTH staging STS (d full-range)
// and frag LDS (dq x kw) conflict-free.
__device__ __forceinline__ int woff(int h, int kb, int d, int w) {
    return ((h * 2 + kb) * 32 + d) * 36 + (w ^ (d >> 3));
}
#define WBUF_WORDS (4 * 32 * 36)                            // 4608 words = 18432 B
#define OFF_W      (64 * XH_STRIDE * 2 * 2)                 // 34816 B (x hi+lo)
#define SMEM_BYTES (OFF_W + 2 * WBUF_WORDS * 4)             // 71680 B

// ---------------------------------------------------------------------------
// K1: one block per input capsule i. 8 warps = (m-tile 0..3) x (n-half 0..1).
// 16 phases of 1 j; W converted once per j, double-buffered via reg prefetch.
// ---------------------------------------------------------------------------
__global__ void __launch_bounds__(256, 2)
uhat_mma(const float* __restrict__ x, const float* __restrict__ W) {
    extern __shared__ char sm[];
    uint16_t* xh = reinterpret_cast<uint16_t*>(sm);
    uint16_t* xl = xh + 64 * XH_STRIDE;
    uint32_t* wb0 = reinterpret_cast<uint32_t*>(sm + OFF_W);
    uint32_t* wb1 = wb0 + WBUF_WORDS;

    const int i = blockIdx.x, tid = threadIdx.x;
    const int wid = tid >> 5, lane = tid & 31;

    const float* Wi = W + (size_t)i * NCAPS * IDIM * ODIM;

    // thread's staging coordinates: 8 pairs, q = r*256+tid -> d = q&31, kp = q>>5
    float p0[8], p1[8];
    auto prefetchW = [&](int j) {
        const float* Wj = Wi + (size_t)j * IDIM * ODIM;
        #pragma unroll
        for (int r = 0; r < 8; ++r) {
            int q = r * 256 + tid;
            int d = q & 31, kp = q >> 5;
            const float* p = Wj + (2 * kp) * ODIM + d;
            p0[r] = __ldcs(p);
            p1[r] = __ldcs(p + ODIM);
        }
    };
    auto convertW = [&](uint32_t* wb) {
        #pragma unroll
        for (int r = 0; r < 8; ++r) {
            int q = r * 256 + tid;
            int d = q & 31, kp = q >> 5;
            int kb = kp >> 5, w = kp & 31;
            wb[woff(0, kb, d, w)] = prmt_hi(p0[r], p1[r]);
            wb[woff(1, kb, d, w)] = lo_pack(p0[r], p1[r]);
        }
    };

    prefetchW(0);

    // stage x[:, i, :] as bf16 hi/lo (rows b, k contiguous)
    for (int q = tid; q < 2048; q += 256) {
        int b = q >> 5, k4 = q & 31;
        float4 v = __ldcs(reinterpret_cast<const float4*>(
                              x + ((size_t)b * ICAPS + i) * IDIM) + k4);
        uint32_t h0 = prmt_hi(v.x, v.y), h1 = prmt_hi(v.z, v.w);
        uint32_t l0 = lo_pack(v.x, v.y), l1 = lo_pack(v.z, v.w);
        *reinterpret_cast<uint2*>(xh + b * XH_STRIDE + k4 * 4) = make_uint2(h0, h1);
        *reinterpret_cast<uint2*>(xl + b * XH_STRIDE + k4 * 4) = make_uint2(l0, l1);
    }
    convertW(wb0);
    __syncthreads();

    // hoist A-frags: warp's m-tile, 8 k-steps, hi+lo (64 regs)
    const int mt = wid & 3, nh = wid >> 2;
    const int m0 = mt * 16;
    uint32_t A[8][2][4];
    {
        const int r0 = m0 + (lane >> 2);
        const int cb = (lane & 3) * 2;
        #pragma unroll
        for (int ks = 0; ks < 8; ++ks) {
            int c0 = ks * 16 + cb;
            A[ks][0][0] = *reinterpret_cast<const uint32_t*>(xh + r0 * XH_STRIDE + c0);
            A[ks][0][1] = *reinterpret_cast<const uint32_t*>(xh + (r0 + 8) * XH_STRIDE + c0);
            A[ks][0][2] = *reinterpret_cast<const uint32_t*>(xh + r0 * XH_STRIDE + c0 + 8);
            A[ks][0][3] = *reinterpret_cast<const uint32_t*>(xh + (r0 + 8) * XH_STRIDE + c0 + 8);
            A[ks][1][0] = *reinterpret_cast<const uint32_t*>(xl + r0 * XH_STRIDE + c0);
            A[ks][1][1] = *reinterpret_cast<const uint32_t*>(xl + (r0 + 8) * XH_STRIDE + c0);
            A[ks][1][2] = *reinterpret_cast<const uint32_t*>(xl + r0 * XH_STRIDE + c0 + 8);
            A[ks][1][3] = *reinterpret_cast<const uint32_t*>(xl + (r0 + 8) * XH_STRIDE + c0 + 8);
        }
    }

    const int lw = lane & 3;     // k-pair within 16 (k = 16ks + 2*lw)
    const int dq = lane >> 2;    // col within n8

    for (int j = 0; j < 16; ++j) {
        uint32_t* wcur = (j & 1) ? wb1 : wb0;
        uint32_t* wnxt = (j & 1) ? wb0 : wb1;
        if (j < 15) prefetchW(j + 1);

        float c[2][4] = {{0.f, 0.f, 0.f, 0.f}, {0.f, 0.f, 0.f, 0.f}};
        #pragma unroll
        for (int ks = 0; ks < 8; ++ks) {
            const int kb = ks >> 2;
            const int w0 = 8 * (ks & 3) + lw;
            #pragma unroll
            for (int nt = 0; nt < 2; ++nt) {
                const int d = nh * 16 + nt * 8 + dq;
                uint32_t bh0 = wcur[woff(0, kb, d, w0)];
                uint32_t bh1 = wcur[woff(0, kb, d, w0 + 4)];
                uint32_t bl0 = wcur[woff(1, kb, d, w0)];
                uint32_t bl1 = wcur[woff(1, kb, d, w0 + 4)];
                mma16816(c[nt], A[ks][0], bh0, bh1);  // Ah*Bh
                mma16816(c[nt], A[ks][0], bl0, bl1);  // Ah*Bl
                mma16816(c[nt], A[ks][1], bh0, bh1);  // Al*Bh
            }
        }

        // epilogue: rows = b, cols = d contiguous
        const int brow = m0 + (lane >> 2);
        const int dc0 = nh * 16 + (lane & 3) * 2;
        #pragma unroll
        for (int nt = 0; nt < 2; ++nt) {
            int d = dc0 + nt * 8;
            *reinterpret_cast<float2*>(
                g_uhat + ((((size_t)brow * ICAPS + i) * NCAPS + j) * ODIM + d)) =
                make_float2(c[nt][0], c[nt][1]);
            *reinterpret_cast<float2*>(
                g_uhat + ((((size_t)(brow + 8) * ICAPS + i) * NCAPS + j) * ODIM + d)) =
                make_float2(c[nt][2], c[nt][3]);
        }

        if (j < 15) convertW(wnxt);
        __syncthreads();
    }
}

// ---------------------------------------------------------------------------
// K2: r=0 partials, c = 1/16. grid (B_, 8), 512 thr: ig = tid>>7 picks i-lane,
// f = tid&127 picks float4 of the 512-float (j,d) space. Contiguous float4.
// ---------------------------------------------------------------------------
__global__ void __launch_bounds__(512)
s_uniform_part() {
    const int b = blockIdx.x, chunk = blockIdx.y, tid = threadIdx.x;
    const int ig = tid >> 7, f = tid & 127;
    const float4* U = reinterpret_cast<const float4*>(
                          g_uhat + ((size_t)b * ICAPS + chunk * 64) * 512) + f;
    float4 acc = make_float4(0.f, 0.f, 0.f, 0.f);
    #pragma unroll 4
    for (int ii = 0; ii < 16; ++ii) {
        float4 u = U[(size_t)(ii * 4 + ig) * 128];
        acc.x += u.x; acc.y += u.y; acc.z += u.z; acc.w += u.w;
    }
    __shared__ float4 smr[4][128];
    smr[ig][f] = acc;
    __syncthreads();
    if (tid < 128) {
        float4 a = smr[0][tid], s;
        s.x = (a.x + smr[1][tid].x + smr[2][tid].x + smr[3][tid].x) * 0.0625f;
        s.y = (a.y + smr[1][tid].y + smr[2][tid].y + smr[3][tid].y) * 0.0625f;
        s.z = (a.z + smr[1][tid].z + smr[2][tid].z + smr[3][tid].z) * 0.0625f;
        s.w = (a.w + smr[1][tid].w + smr[2][tid].w + smr[3][tid].w) * 0.0625f;
        reinterpret_cast<float4*>(
            g_part + ((size_t)chunk * B_ + b) * 512)[tid] = s;
    }
}

// ---------------------------------------------------------------------------
// K3: fused routing pass. grid (B_, 8), 256 thr. Warp handles 4 i per step via
// 8-lane segments; thread owns d-quad dq (float4). 2 steps cover 64 i.
// ---------------------------------------------------------------------------
__global__ void __launch_bounds__(256)
fused_route(int addPrev) {
    const int b = blockIdx.x, chunk = blockIdx.y;
    const int wid = threadIdx.x >> 5, lane = threadIdx.x & 31;
    const int seg = lane >> 3, dq = lane & 7;

    __shared__ float vsh[NCAPS][ODIM];     // 2 KB
    __shared__ float smr[8][NCAPS][ODIM];  // 16 KB
    for (int q = threadIdx.x; q < 512; q += 256)
        (&vsh[0][0])[q] = g_v[(size_t)b * 512 + q];
    __syncthreads();

    float4 sacc[NCAPS];
    #pragma unroll
    for (int j = 0; j < NCAPS; ++j) sacc[j] = make_float4(0.f, 0.f, 0.f, 0.f);

    #pragma unroll
    for (int step = 0; step < 2; ++step) {
        const int i = chunk * 64 + step * 32 + wid * 4 + seg;
        const float4* U = reinterpret_cast<const float4*>(
                              g_uhat + ((size_t)b * ICAPS + i) * 512);

        float bj[NCAPS];
        #pragma unroll
        for (int j = 0; j < NCAPS; ++j) {
            float4 u = U[j * 8 + dq];
            const float4 vj = *reinterpret_cast<const float4*>(&vsh[j][dq * 4]);
            float p = u.x * vj.x + u.y * vj.y + u.z * vj.z + u.w * vj.w;
            p += __shfl_xor_sync(0xffffffffu, p, 1);
            p += __shfl_xor_sync(0xffffffffu, p, 2);
            p += __shfl_xor_sync(0xffffffffu, p, 4);
            bj[j] = p;
        }

        float* Bp = g_b + ((size_t)b * ICAPS + i) * NCAPS;
        if (addPrev) {
            float bp0 = Bp[dq], bp1 = Bp[dq + 8];
            #pragma unroll
            for (int j = 0; j < NCAPS; ++j) {
                float src = (j < 8) ? bp0 : bp1;
                bj[j] += __shfl_sync(0xffffffffu, src, (lane & 24) | (j & 7));
            }
        } else {
            float b0 = 0.f, b1 = 0.f;
            #pragma unroll
            for (int j = 0; j < 8; ++j)  b0 = (dq == j) ? bj[j] : b0;
            #pragma unroll
            for (int j = 8; j < 16; ++j) b1 = (dq == j - 8) ? bj[j] : b1;
            Bp[dq] = b0;
            Bp[dq + 8] = b1;
        }

        float m = bj[0];
        #pragma unroll
        for (int j = 1; j < NCAPS; ++j) m = fmaxf(m, bj[j]);
        float sum = 0.f;
        #pragma unroll
        for (int j = 0; j < NCAPS; ++j) { bj[j] = __expf(bj[j] - m); sum += bj[j]; }
        const float inv = 1.f / sum;

        #pragma unroll
        for (int j = 0; j < NCAPS; ++j) {
            float4 u = U[j * 8 + dq];   // L1 hit (same addresses as dot pass)
            float cc = bj[j] * inv;
            sacc[j].x = fmaf(cc, u.x, sacc[j].x);
            sacc[j].y = fmaf(cc, u.y, sacc[j].y);
            sacc[j].z = fmaf(cc, u.z, sacc[j].z);
            sacc[j].w = fmaf(cc, u.w, sacc[j].w);
        }
    }

    // reduce across 4 segments (lane strides 8, 16)
    #pragma unroll
    for (int j = 0; j < NCAPS; ++j) {
        sacc[j].x += __shfl_xor_sync(0xffffffffu, sacc[j].x, 8);
        sacc[j].x += __shfl_xor_sync(0xffffffffu, sacc[j].x, 16);
        sacc[j].y += __shfl_xor_sync(0xffffffffu, sacc[j].y, 8);
        sacc[j].y += __shfl_xor_sync(0xffffffffu, sacc[j].y, 16);
        sacc[j].z += __shfl_xor_sync(0xffffffffu, sacc[j].z, 8);
        sacc[j].z += __shfl_xor_sync(0xffffffffu, sacc[j].z, 16);
        sacc[j].w += __shfl_xor_sync(0xffffffffu, sacc[j].w, 8);
        sacc[j].w += __shfl_xor_sync(0xffffffffu, sacc[j].w, 16);
    }
    if (seg == 0) {
        #pragma unroll
        for (int j = 0; j < NCAPS; ++j)
            *reinterpret_cast<float4*>(&smr[wid][j][dq * 4]) = sacc[j];
    }
    __syncthreads();
    for (int q = threadIdx.x; q < 512; q += 256) {
        int j = q >> 5, d = q & 31;
        float s = 0.f;
        #pragma unroll
        for (int w = 0; w < 8; ++w) s += smr[w][j][d];
        g_part[((size_t)chunk * B_ + b) * 512 + q] = s;
    }
}

// ---------------------------------------------------------------------------
// K4: reduce 8 chunks, squash, write g_v or final out. grid B_, 512 thr.
// ---------------------------------------------------------------------------
__global__ void __launch_bounds__(512)
squash_reduce(float* __restrict__ out, int final_iter) {
    const int b = blockIdx.x, tid = threadIdx.x;
    float s = 0.f;
    #pragma unroll
    for (int c = 0; c < 8; ++c)
        s += g_part[((size_t)c * B_ + b) * 512 + tid];
    float ss = s * s;
    #pragma unroll
    for (int o = 16; o; o >>= 1) ss += __shfl_xor_sync(0xffffffffu, ss, o);
    float scale = ss / (1.f + ss) * rsqrtf(ss + 1e-7f);
    float* dst = final_iter ? out : g_v;
    dst[(size_t)b * 512 + tid] = scale * s;
}

// ---------------------------------------------------------------------------
extern "C" void kernel_launch(void* const* d_in, const int* in_sizes, int n_in,
                              void* d_out, int out_size) {
    const float* x = (const float*)d_in[0];
    const float* W = (const float*)d_in[1];
    float* out = (float*)d_out;

    cudaFuncSetAttribute(uhat_mma, cudaFuncAttributeMaxDynamicSharedMemorySize,
                         SMEM_BYTES);

    uhat_mma<<<ICAPS, 256, SMEM_BYTES>>>(x, W);

    s_uniform_part<<<dim3(B_, 8), 512>>>();   // r=0 partials
    squash_reduce<<<B_, 512>>>(out, 0);       // -> v
    fused_route<<<dim3(B_, 8), 256>>>(0);     // r=1
    squash_reduce<<<B_, 512>>>(out, 0);       // -> v
    fused_route<<<dim3(B_, 8), 256>>>(1);     // r=2
    squash_reduce<<<B_, 512>>>(out, 1);       // -> out
}

// round 12
// speedup vs baseline: 3.2755x; 1.0159x over previous
#include <cuda_runtime.h>
#include <cuda_bf16.h>
#include <cstdint>

// CapsuleLayer dynamic routing.
//   inputs: (64, 512, 128) fp32 ; W: (512, 16, 128, 32) fp32 ; num_routing=3
//   out: (64, 16, 32) fp32
//
// K1 uhat_mma      : mma.sync m16n8k16 bf16 split precision (Ah*Bh+Ah*Bl+Al*Bh).
//                    (at its HMMA instruction-rate floor; unchanged from R10)
// K2 s_uniform_part: r=0 weighted-sum partials (c = 1/16), float4, 16 chunks.
// K3 fused_route   : agreement dot + bias + softmax + weighted-sum partials.
//                    v3: 1 i per 8-lane segment, sacc in two j-halves (32 regs),
//                    asm reloads to stop CSE -> low regs, high occupancy.
// K4 squash_reduce : reduce 16 chunk partials + squash -> v or final out.

#define B_    64
#define ICAPS 512
#define IDIM  128
#define NCAPS 16
#define ODIM  32

__device__ float g_uhat[(size_t)B_ * ICAPS * NCAPS * ODIM];  // 67 MB
__device__ float g_b[(size_t)B_ * ICAPS * NCAPS];
__device__ float g_v[(size_t)B_ * NCAPS * ODIM];
__device__ float g_part[(size_t)16 * B_ * NCAPS * ODIM];     // 2 MB

// ---------------- helpers ----------------
__device__ __forceinline__ uint32_t prmt_hi(float v0, float v1) {
    uint32_t r;
    asm("prmt.b32 %0, %1, %2, 0x7632;"
        : "=r"(r) : "r"(__float_as_uint(v0)), "r"(__float_as_uint(v1)));
    return r;
}
__device__ __forceinline__ uint32_t lo_pack(float v0, float v1) {
    float h0 = __uint_as_float(__float_as_uint(v0) & 0xFFFF0000u);
    float h1 = __uint_as_float(__float_as_uint(v1) & 0xFFFF0000u);
    float l0 = v0 - h0, l1 = v1 - h1;
    uint32_t r;
    asm("cvt.rn.bf16x2.f32 %0, %1, %2;" : "=r"(r) : "f"(l1), "f"(l0));
    return r;
}
__device__ __forceinline__ void mma16816(float* c, const uint32_t* a,
                                         uint32_t b0, uint32_t b1) {
    asm volatile(
        "mma.sync.aligned.m16n8k16.row.col.f32.bf16.bf16.f32 "
        "{%0,%1,%2,%3}, {%4,%5,%6,%7}, {%8,%9}, {%0,%1,%2,%3};"
        : "+f"(c[0]), "+f"(c[1]), "+f"(c[2]), "+f"(c[3])
        : "r"(a[0]), "r"(a[1]), "r"(a[2]), "r"(a[3]), "r"(b0), "r"(b1));
}
// uncacheable-by-compiler global v4 load (prevents cross-pass register CSE)
__device__ __forceinline__ float4 ldg4_nc(const float4* p) {
    float4 v;
    asm volatile("ld.global.nc.v4.f32 {%0,%1,%2,%3}, [%4];"
                 : "=f"(v.x), "=f"(v.y), "=f"(v.z), "=f"(v.w) : "l"(p));
    return v;
}

#define XH_STRIDE 136
__device__ __forceinline__ int woff(int h, int kb, int d, int w) {
    return ((h * 2 + kb) * 32 + d) * 36 + (w ^ (d >> 3));
}
#define WBUF_WORDS (4 * 32 * 36)
#define OFF_W      (64 * XH_STRIDE * 2 * 2)
#define SMEM_BYTES (OFF_W + 2 * WBUF_WORDS * 4)   // 71680 B

// ---------------------------------------------------------------------------
// K1: u_hat GEMM (unchanged from R10 — at HMMA floor).
// ---------------------------------------------------------------------------
__global__ void __launch_bounds__(256, 2)
uhat_mma(const float* __restrict__ x, const float* __restrict__ W) {
    extern __shared__ char sm[];
    uint16_t* xh = reinterpret_cast<uint16_t*>(sm);
    uint16_t* xl = xh + 64 * XH_STRIDE;
    uint32_t* wb0 = reinterpret_cast<uint32_t*>(sm + OFF_W);
    uint32_t* wb1 = wb0 + WBUF_WORDS;

    const int i = blockIdx.x, tid = threadIdx.x;
    const int wid = tid >> 5, lane = tid & 31;
    const float* Wi = W + (size_t)i * NCAPS * IDIM * ODIM;

    float p0[8], p1[8];
    auto prefetchW = [&](int j) {
        const float* Wj = Wi + (size_t)j * IDIM * ODIM;
        #pragma unroll
        for (int r = 0; r < 8; ++r) {
            int q = r * 256 + tid;
            int d = q & 31, kp = q >> 5;
            const float* p = Wj + (2 * kp) * ODIM + d;
            p0[r] = __ldcs(p);
            p1[r] = __ldcs(p + ODIM);
        }
    };
    auto convertW = [&](uint32_t* wb) {
        #pragma unroll
        for (int r = 0; r < 8; ++r) {
            int q = r * 256 + tid;
            int d = q & 31, kp = q >> 5;
            int kb = kp >> 5, w = kp & 31;
            wb[woff(0, kb, d, w)] = prmt_hi(p0[r], p1[r]);
            wb[woff(1, kb, d, w)] = lo_pack(p0[r], p1[r]);
        }
    };

    prefetchW(0);
    for (int q = tid; q < 2048; q += 256) {
        int b = q >> 5, k4 = q & 31;
        float4 v = __ldcs(reinterpret_cast<const float4*>(
                              x + ((size_t)b * ICAPS + i) * IDIM) + k4);
        uint32_t h0 = prmt_hi(v.x, v.y), h1 = prmt_hi(v.z, v.w);
        uint32_t l0 = lo_pack(v.x, v.y), l1 = lo_pack(v.z, v.w);
        *reinterpret_cast<uint2*>(xh + b * XH_STRIDE + k4 * 4) = make_uint2(h0, h1);
        *reinterpret_cast<uint2*>(xl + b * XH_STRIDE + k4 * 4) = make_uint2(l0, l1);
    }
    convertW(wb0);
    __syncthreads();

    const int mt = wid & 3, nh = wid >> 2;
    const int m0 = mt * 16;
    uint32_t A[8][2][4];
    {
        const int r0 = m0 + (lane >> 2);
        const int cb = (lane & 3) * 2;
        #pragma unroll
        for (int ks = 0; ks < 8; ++ks) {
            int c0 = ks * 16 + cb;
            A[ks][0][0] = *reinterpret_cast<const uint32_t*>(xh + r0 * XH_STRIDE + c0);
            A[ks][0][1] = *reinterpret_cast<const uint32_t*>(xh + (r0 + 8) * XH_STRIDE + c0);
            A[ks][0][2] = *reinterpret_cast<const uint32_t*>(xh + r0 * XH_STRIDE + c0 + 8);
            A[ks][0][3] = *reinterpret_cast<const uint32_t*>(xh + (r0 + 8) * XH_STRIDE + c0 + 8);
            A[ks][1][0] = *reinterpret_cast<const uint32_t*>(xl + r0 * XH_STRIDE + c0);
            A[ks][1][1] = *reinterpret_cast<const uint32_t*>(xl + (r0 + 8) * XH_STRIDE + c0);
            A[ks][1][2] = *reinterpret_cast<const uint32_t*>(xl + r0 * XH_STRIDE + c0 + 8);
            A[ks][1][3] = *reinterpret_cast<const uint32_t*>(xl + (r0 + 8) * XH_STRIDE + c0 + 8);
        }
    }

    const int lw = lane & 3;
    const int dq = lane >> 2;

    for (int j = 0; j < 16; ++j) {
        uint32_t* wcur = (j & 1) ? wb1 : wb0;
        uint32_t* wnxt = (j & 1) ? wb0 : wb1;
        if (j < 15) prefetchW(j + 1);

        float c[2][4] = {{0.f, 0.f, 0.f, 0.f}, {0.f, 0.f, 0.f, 0.f}};
        #pragma unroll
        for (int ks = 0; ks < 8; ++ks) {
            const int kb = ks >> 2;
            const int w0 = 8 * (ks & 3) + lw;
            #pragma unroll
            for (int nt = 0; nt < 2; ++nt) {
                const int d = nh * 16 + nt * 8 + dq;
                uint32_t bh0 = wcur[woff(0, kb, d, w0)];
                uint32_t bh1 = wcur[woff(0, kb, d, w0 + 4)];
                uint32_t bl0 = wcur[woff(1, kb, d, w0)];
                uint32_t bl1 = wcur[woff(1, kb, d, w0 + 4)];
                mma16816(c[nt], A[ks][0], bh0, bh1);
                mma16816(c[nt], A[ks][0], bl0, bl1);
                mma16816(c[nt], A[ks][1], bh0, bh1);
            }
        }

        const int brow = m0 + (lane >> 2);
        const int dc0 = nh * 16 + (lane & 3) * 2;
        #pragma unroll
        for (int nt = 0; nt < 2; ++nt) {
            int d = dc0 + nt * 8;
            *reinterpret_cast<float2*>(
                g_uhat + ((((size_t)brow * ICAPS + i) * NCAPS + j) * ODIM + d)) =
                make_float2(c[nt][0], c[nt][1]);
            *reinterpret_cast<float2*>(
                g_uhat + ((((size_t)(brow + 8) * ICAPS + i) * NCAPS + j) * ODIM + d)) =
                make_float2(c[nt][2], c[nt][3]);
        }

        if (j < 15) convertW(wnxt);
        __syncthreads();
    }
}

// ---------------------------------------------------------------------------
// K2: r=0 partials, c = 1/16. grid (B_, 16): 32 i/chunk. 512 thr.
// ---------------------------------------------------------------------------
__global__ void __launch_bounds__(512)
s_uniform_part() {
    const int b = blockIdx.x, chunk = blockIdx.y, tid = threadIdx.x;
    const int ig = tid >> 7, f = tid & 127;
    const float4* U = reinterpret_cast<const float4*>(
                          g_uhat + ((size_t)b * ICAPS + chunk * 32) * 512) + f;
    float4 acc = make_float4(0.f, 0.f, 0.f, 0.f);
    #pragma unroll 4
    for (int ii = 0; ii < 8; ++ii) {
        float4 u = U[(size_t)(ii * 4 + ig) * 128];
        acc.x += u.x; acc.y += u.y; acc.z += u.z; acc.w += u.w;
    }
    __shared__ float4 smr[4][128];
    smr[ig][f] = acc;
    __syncthreads();
    if (tid < 128) {
        float4 a = smr[0][tid], s;
        s.x = (a.x + smr[1][tid].x + smr[2][tid].x + smr[3][tid].x) * 0.0625f;
        s.y = (a.y + smr[1][tid].y + smr[2][tid].y + smr[3][tid].y) * 0.0625f;
        s.z = (a.z + smr[1][tid].z + smr[2][tid].z + smr[3][tid].z) * 0.0625f;
        s.w = (a.w + smr[1][tid].w + smr[2][tid].w + smr[3][tid].w) * 0.0625f;
        reinterpret_cast<float4*>(
            g_part + ((size_t)chunk * B_ + b) * 512)[tid] = s;
    }
}

// ---------------------------------------------------------------------------
// K3: fused routing pass v3. grid (B_, 16), 256 thr. Warp = 4 i (8-lane segs),
// one step. sacc in two j-halves of 8 (32 regs); asm reloads defeat CSE.
// ---------------------------------------------------------------------------
__global__ void __launch_bounds__(256)
fused_route(int addPrev) {
    const int b = blockIdx.x, chunk = blockIdx.y;
    const int wid = threadIdx.x >> 5, lane = threadIdx.x & 31;
    const int seg = lane >> 3, dq = lane & 7;

    __shared__ float vsh[512];             // 2 KB
    __shared__ float smr[8][NCAPS][ODIM];  // 16 KB
    for (int q = threadIdx.x; q < 512; q += 256)
        vsh[q] = g_v[(size_t)b * 512 + q];
    __syncthreads();

    const int i = chunk * 32 + wid * 4 + seg;
    const float4* U = reinterpret_cast<const float4*>(
                          g_uhat + ((size_t)b * ICAPS + i) * 512);

    // pass 1: agreement dots
    float bj[NCAPS];
    #pragma unroll
    for (int j = 0; j < NCAPS; ++j) {
        float4 u = U[j * 8 + dq];
        const float4 vj = *reinterpret_cast<const float4*>(&vsh[j * 32 + dq * 4]);
        float p = u.x * vj.x + u.y * vj.y + u.z * vj.z + u.w * vj.w;
        p += __shfl_xor_sync(0xffffffffu, p, 1);
        p += __shfl_xor_sync(0xffffffffu, p, 2);
        p += __shfl_xor_sync(0xffffffffu, p, 4);
        bj[j] = p;
    }

    float* Bp = g_b + ((size_t)b * ICAPS + i) * NCAPS;
    if (addPrev) {
        float bp0 = Bp[dq], bp1 = Bp[dq + 8];
        #pragma unroll
        for (int j = 0; j < NCAPS; ++j) {
            float src = (j < 8) ? bp0 : bp1;
            bj[j] += __shfl_sync(0xffffffffu, src, (lane & 24) | (j & 7));
        }
    } else {
        float b0 = 0.f, b1 = 0.f;
        #pragma unroll
        for (int j = 0; j < 8; ++j)  b0 = (dq == j) ? bj[j] : b0;
        #pragma unroll
        for (int j = 8; j < 16; ++j) b1 = (dq == j - 8) ? bj[j] : b1;
        Bp[dq] = b0;
        Bp[dq + 8] = b1;
    }

    // softmax over j
    float m = bj[0];
    #pragma unroll
    for (int j = 1; j < NCAPS; ++j) m = fmaxf(m, bj[j]);
    float sum = 0.f;
    #pragma unroll
    for (int j = 0; j < NCAPS; ++j) { bj[j] = __expf(bj[j] - m); sum += bj[j]; }
    const float inv = 1.f / sum;

    // pass 2: weighted sum, two j-halves to cap register pressure
    #pragma unroll
    for (int h = 0; h < 2; ++h) {
        float4 sacc[8];
        #pragma unroll
        for (int jj = 0; jj < 8; ++jj) sacc[jj] = make_float4(0.f, 0.f, 0.f, 0.f);
        #pragma unroll
        for (int jj = 0; jj < 8; ++jj) {
            const int j = h * 8 + jj;
            float4 u = ldg4_nc(U + j * 8 + dq);   // L1 hit; not CSE-able
            float cc = bj[j] * inv;
            sacc[jj].x = fmaf(cc, u.x, sacc[jj].x);
            sacc[jj].y = fmaf(cc, u.y, sacc[jj].y);
            sacc[jj].z = fmaf(cc, u.z, sacc[jj].z);
            sacc[jj].w = fmaf(cc, u.w, sacc[jj].w);
        }
        // reduce across the warp's 4 segments
        #pragma unroll
        for (int jj = 0; jj < 8; ++jj) {
            sacc[jj].x += __shfl_xor_sync(0xffffffffu, sacc[jj].x, 8);
            sacc[jj].x += __shfl_xor_sync(0xffffffffu, sacc[jj].x, 16);
            sacc[jj].y += __shfl_xor_sync(0xffffffffu, sacc[jj].y, 8);
            sacc[jj].y += __shfl_xor_sync(0xffffffffu, sacc[jj].y, 16);
            sacc[jj].z += __shfl_xor_sync(0xffffffffu, sacc[jj].z, 8);
            sacc[jj].z += __shfl_xor_sync(0xffffffffu, sacc[jj].z, 16);
            sacc[jj].w += __shfl_xor_sync(0xffffffffu, sacc[jj].w, 8);
            sacc[jj].w += __shfl_xor_sync(0xffffffffu, sacc[jj].w, 16);
        }
        if (seg == 0) {
            #pragma unroll
            for (int jj = 0; jj < 8; ++jj)
                *reinterpret_cast<float4*>(&smr[wid][h * 8 + jj][dq * 4]) = sacc[jj];
        }
    }
    __syncthreads();
    for (int q = threadIdx.x; q < 512; q += 256) {
        int j = q >> 5, d = q & 31;
        float s = 0.f;
        #pragma unroll
        for (int w = 0; w < 8; ++w) s += smr[w][j][d];
        g_part[((size_t)chunk * B_ + b) * 512 + q] = s;
    }
}

// ---------------------------------------------------------------------------
// K4: reduce 16 chunks, squash, write g_v or final out. grid B_, 512 thr.
// ---------------------------------------------------------------------------
__global__ void __launch_bounds__(512)
squash_reduce(float* __restrict__ out, int final_iter) {
    const int b = blockIdx.x, tid = threadIdx.x;
    float s = 0.f;
    #pragma unroll
    for (int c = 0; c < 16; ++c)
        s += g_part[((size_t)c * B_ + b) * 512 + tid];
    float ss = s * s;
    #pragma unroll
    for (int o = 16; o; o >>= 1) ss += __shfl_xor_sync(0xffffffffu, ss, o);
    float scale = ss / (1.f + ss) * rsqrtf(ss + 1e-7f);
    float* dst = final_iter ? out : g_v;
    dst[(size_t)b * 512 + tid] = scale * s;
}

// ---------------------------------------------------------------------------
extern "C" void kernel_launch(void* const* d_in, const int* in_sizes, int n_in,
                              void* d_out, int out_size) {
    const float* x = (const float*)d_in[0];
    const float* W = (const float*)d_in[1];
    float* out = (float*)d_out;

    cudaFuncSetAttribute(uhat_mma, cudaFuncAttributeMaxDynamicSharedMemorySize,
                         SMEM_BYTES);

    uhat_mma<<<ICAPS, 256, SMEM_BYTES>>>(x, W);

    s_uniform_part<<<dim3(B_, 16), 512>>>();  // r=0 partials
    squash_reduce<<<B_, 512>>>(out, 0);       // -> v
    fused_route<<<dim3(B_, 16), 256>>>(0);    // r=1
    squash_reduce<<<B_, 512>>>(out, 0);       // -> v
    fused_route<<<dim3(B_, 16), 256>>>(1);    // r=2
    squash_reduce<<<B_, 512>>>(out, 1);       // -> out
}

// round 13
// speedup vs baseline: 3.6787x; 1.1231x over previous
#include <cuda_runtime.h>
#include <cuda_fp16.h>
#include <cstdint>

// CapsuleLayer dynamic routing.
//   inputs: (64, 512, 128) fp32 ; W: (512, 16, 128, 32) fp32 ; num_routing=3
//   out: (64, 16, 32) fp32
//
// K1 uhat_mma      : mma.sync m16n8k16 **fp16** split precision, 2 groups:
//                    u_hat = (Ah+Al)*Bh  (A = x hi+lo, B = W hi only).
//                    Dropped A*Bl term ~2^-11 relative (~3e-4, < 1e-3 tol).
// K2 s_uniform_part: r=0 weighted-sum partials (c = 1/16), float4, 16 chunks.
// K3 fused_route   : agreement dot + bias + softmax + weighted-sum partials.
// K4 squash_reduce : reduce 16 chunk partials + squash -> v or final out.

#define B_    64
#define ICAPS 512
#define IDIM  128
#define NCAPS 16
#define ODIM  32

__device__ float g_uhat[(size_t)B_ * ICAPS * NCAPS * ODIM];  // 67 MB
__device__ float g_b[(size_t)B_ * ICAPS * NCAPS];
__device__ float g_v[(size_t)B_ * NCAPS * ODIM];
__device__ float g_part[(size_t)16 * B_ * NCAPS * ODIM];     // 2 MB

// ---------------- helpers ----------------
// packed f16x2 of (v0 -> low, v1 -> high): RN
__device__ __forceinline__ uint32_t pack_f16(float v0, float v1) {
    uint32_t r;
    asm("cvt.rn.f16x2.f32 %0, %1, %2;" : "=r"(r) : "f"(v1), "f"(v0));
    return r;
}
// split (v0, v1) into fp16 hi pair + fp16 lo (residual) pair; residual exact
__device__ __forceinline__ void split2_f16(float v0, float v1,
                                           uint32_t& h, uint32_t& l) {
    asm("cvt.rn.f16x2.f32 %0, %1, %2;" : "=r"(h) : "f"(v1), "f"(v0));
    float f0, f1;
    asm("{ .reg .b16 x,y; mov.b32 {x,y}, %2; cvt.f32.f16 %0, x; cvt.f32.f16 %1, y; }"
        : "=f"(f0), "=f"(f1) : "r"(h));
    asm("cvt.rn.f16x2.f32 %0, %1, %2;" : "=r"(l) : "f"(v1 - f1), "f"(v0 - f0));
}
__device__ __forceinline__ void mma16816(float* c, const uint32_t* a,
                                         uint32_t b0, uint32_t b1) {
    asm volatile(
        "mma.sync.aligned.m16n8k16.row.col.f32.f16.f16.f32 "
        "{%0,%1,%2,%3}, {%4,%5,%6,%7}, {%8,%9}, {%0,%1,%2,%3};"
        : "+f"(c[0]), "+f"(c[1]), "+f"(c[2]), "+f"(c[3])
        : "r"(a[0]), "r"(a[1]), "r"(a[2]), "r"(a[3]), "r"(b0), "r"(b1));
}
// uncacheable-by-compiler global v4 load (prevents cross-pass register CSE)
__device__ __forceinline__ float4 ldg4_nc(const float4* p) {
    float4 v;
    asm volatile("ld.global.nc.v4.f32 {%0,%1,%2,%3}, [%4];"
                 : "=f"(v.x), "=f"(v.y), "=f"(v.z), "=f"(v.w) : "l"(p));
    return v;
}

#define XH_STRIDE 136
// Converted-W (hi only) word offset: kb (k>>6), d (0..31), w = k-pair in kb.
// Pitch 36 + XOR swizzle: conflict-free for both staging STS and frag LDS.
__device__ __forceinline__ int woff(int kb, int d, int w) {
    return (kb * 32 + d) * 36 + (w ^ (d >> 3));
}
#define WBUF_WORDS (2 * 32 * 36)                   // 2304 words = 9216 B
#define OFF_W      (64 * XH_STRIDE * 2 * 2)        // 34816 B (x hi+lo)
#define SMEM_BYTES (OFF_W + 2 * WBUF_WORDS * 4)    // 53248 B

// ---------------------------------------------------------------------------
// K1: u_hat GEMM. One block per i; 8 warps = (m-tile 0..3) x (n-half 0..1).
// 16 phases of 1 j; W hi converted once per j, double-buffered via reg prefetch.
// ---------------------------------------------------------------------------
__global__ void __launch_bounds__(256, 2)
uhat_mma(const float* __restrict__ x, const float* __restrict__ W) {
    extern __shared__ char sm[];
    uint16_t* xh = reinterpret_cast<uint16_t*>(sm);
    uint16_t* xl = xh + 64 * XH_STRIDE;
    uint32_t* wb0 = reinterpret_cast<uint32_t*>(sm + OFF_W);
    uint32_t* wb1 = wb0 + WBUF_WORDS;

    const int i = blockIdx.x, tid = threadIdx.x;
    const int wid = tid >> 5, lane = tid & 31;
    const float* Wi = W + (size_t)i * NCAPS * IDIM * ODIM;

    float p0[8], p1[8];
    auto prefetchW = [&](int j) {
        const float* Wj = Wi + (size_t)j * IDIM * ODIM;
        #pragma unroll
        for (int r = 0; r < 8; ++r) {
            int q = r * 256 + tid;
            int d = q & 31, kp = q >> 5;
            const float* p = Wj + (2 * kp) * ODIM + d;
            p0[r] = __ldcs(p);
            p1[r] = __ldcs(p + ODIM);
        }
    };
    auto convertW = [&](uint32_t* wb) {
        #pragma unroll
        for (int r = 0; r < 8; ++r) {
            int q = r * 256 + tid;
            int d = q & 31, kp = q >> 5;
            int kb = kp >> 5, w = kp & 31;
            wb[woff(kb, d, w)] = pack_f16(p0[r], p1[r]);   // hi only
        }
    };

    prefetchW(0);
    // stage x[:, i, :] as fp16 hi/lo (rows b, k contiguous)
    for (int q = tid; q < 2048; q += 256) {
        int b = q >> 5, k4 = q & 31;
        float4 v = __ldcs(reinterpret_cast<const float4*>(
                              x + ((size_t)b * ICAPS + i) * IDIM) + k4);
        uint32_t h0, l0, h1, l1;
        split2_f16(v.x, v.y, h0, l0);
        split2_f16(v.z, v.w, h1, l1);
        *reinterpret_cast<uint2*>(xh + b * XH_STRIDE + k4 * 4) = make_uint2(h0, h1);
        *reinterpret_cast<uint2*>(xl + b * XH_STRIDE + k4 * 4) = make_uint2(l0, l1);
    }
    convertW(wb0);
    __syncthreads();

    const int mt = wid & 3, nh = wid >> 2;
    const int m0 = mt * 16;
    uint32_t A[8][2][4];
    {
        const int r0 = m0 + (lane >> 2);
        const int cb = (lane & 3) * 2;
        #pragma unroll
        for (int ks = 0; ks < 8; ++ks) {
            int c0 = ks * 16 + cb;
            A[ks][0][0] = *reinterpret_cast<const uint32_t*>(xh + r0 * XH_STRIDE + c0);
            A[ks][0][1] = *reinterpret_cast<const uint32_t*>(xh + (r0 + 8) * XH_STRIDE + c0);
            A[ks][0][2] = *reinterpret_cast<const uint32_t*>(xh + r0 * XH_STRIDE + c0 + 8);
            A[ks][0][3] = *reinterpret_cast<const uint32_t*>(xh + (r0 + 8) * XH_STRIDE + c0 + 8);
            A[ks][1][0] = *reinterpret_cast<const uint32_t*>(xl + r0 * XH_STRIDE + c0);
            A[ks][1][1] = *reinterpret_cast<const uint32_t*>(xl + (r0 + 8) * XH_STRIDE + c0);
            A[ks][1][2] = *reinterpret_cast<const uint32_t*>(xl + r0 * XH_STRIDE + c0 + 8);
            A[ks][1][3] = *reinterpret_cast<const uint32_t*>(xl + (r0 + 8) * XH_STRIDE + c0 + 8);
        }
    }

    const int lw = lane & 3;
    const int dq = lane >> 2;

    for (int j = 0; j < 16; ++j) {
        uint32_t* wcur = (j & 1) ? wb1 : wb0;
        uint32_t* wnxt = (j & 1) ? wb0 : wb1;
        if (j < 15) prefetchW(j + 1);

        float c[2][4] = {{0.f, 0.f, 0.f, 0.f}, {0.f, 0.f, 0.f, 0.f}};
        #pragma unroll
        for (int ks = 0; ks < 8; ++ks) {
            const int kb = ks >> 2;
            const int w0 = 8 * (ks & 3) + lw;
            #pragma unroll
            for (int nt = 0; nt < 2; ++nt) {
                const int d = nh * 16 + nt * 8 + dq;
                uint32_t bh0 = wcur[woff(kb, d, w0)];
                uint32_t bh1 = wcur[woff(kb, d, w0 + 4)];
                mma16816(c[nt], A[ks][0], bh0, bh1);  // Ah*Bh
                mma16816(c[nt], A[ks][1], bh0, bh1);  // Al*Bh
            }
        }

        const int brow = m0 + (lane >> 2);
        const int dc0 = nh * 16 + (lane & 3) * 2;
        #pragma unroll
        for (int nt = 0; nt < 2; ++nt) {
            int d = dc0 + nt * 8;
            *reinterpret_cast<float2*>(
                g_uhat + ((((size_t)brow * ICAPS + i) * NCAPS + j) * ODIM + d)) =
                make_float2(c[nt][0], c[nt][1]);
            *reinterpret_cast<float2*>(
                g_uhat + ((((size_t)(brow + 8) * ICAPS + i) * NCAPS + j) * ODIM + d)) =
                make_float2(c[nt][2], c[nt][3]);
        }

        if (j < 15) convertW(wnxt);
        __syncthreads();
    }
}

// ---------------------------------------------------------------------------
// K2: r=0 partials, c = 1/16. grid (B_, 16): 32 i/chunk. 512 thr.
// ---------------------------------------------------------------------------
__global__ void __launch_bounds__(512)
s_uniform_part() {
    const int b = blockIdx.x, chunk = blockIdx.y, tid = threadIdx.x;
    const int ig = tid >> 7, f = tid & 127;
    const float4* U = reinterpret_cast<const float4*>(
                          g_uhat + ((size_t)b * ICAPS + chunk * 32) * 512) + f;
    float4 acc = make_float4(0.f, 0.f, 0.f, 0.f);
    #pragma unroll 4
    for (int ii = 0; ii < 8; ++ii) {
        float4 u = U[(size_t)(ii * 4 + ig) * 128];
        acc.x += u.x; acc.y += u.y; acc.z += u.z; acc.w += u.w;
    }
    __shared__ float4 smr[4][128];
    smr[ig][f] = acc;
    __syncthreads();
    if (tid < 128) {
        float4 a = smr[0][tid], s;
        s.x = (a.x + smr[1][tid].x + smr[2][tid].x + smr[3][tid].x) * 0.0625f;
        s.y = (a.y + smr[1][tid].y + smr[2][tid].y + smr[3][tid].y) * 0.0625f;
        s.z = (a.z + smr[1][tid].z + smr[2][tid].z + smr[3][tid].z) * 0.0625f;
        s.w = (a.w + smr[1][tid].w + smr[2][tid].w + smr[3][tid].w) * 0.0625f;
        reinterpret_cast<float4*>(
            g_part + ((size_t)chunk * B_ + b) * 512)[tid] = s;
    }
}

// ---------------------------------------------------------------------------
// K3: fused routing pass. grid (B_, 16), 256 thr. Warp = 4 i (8-lane segs).
// ---------------------------------------------------------------------------
__global__ void __launch_bounds__(256)
fused_route(int addPrev) {
    const int b = blockIdx.x, chunk = blockIdx.y;
    const int wid = threadIdx.x >> 5, lane = threadIdx.x & 31;
    const int seg = lane >> 3, dq = lane & 7;

    __shared__ float vsh[512];             // 2 KB
    __shared__ float smr[8][NCAPS][ODIM];  // 16 KB
    for (int q = threadIdx.x; q < 512; q += 256)
        vsh[q] = g_v[(size_t)b * 512 + q];
    __syncthreads();

    const int i = chunk * 32 + wid * 4 + seg;
    const float4* U = reinterpret_cast<const float4*>(
                          g_uhat + ((size_t)b * ICAPS + i) * 512);

    // pass 1: agreement dots
    float bj[NCAPS];
    #pragma unroll
    for (int j = 0; j < NCAPS; ++j) {
        float4 u = U[j * 8 + dq];
        const float4 vj = *reinterpret_cast<const float4*>(&vsh[j * 32 + dq * 4]);
        float p = u.x * vj.x + u.y * vj.y + u.z * vj.z + u.w * vj.w;
        p += __shfl_xor_sync(0xffffffffu, p, 1);
        p += __shfl_xor_sync(0xffffffffu, p, 2);
        p += __shfl_xor_sync(0xffffffffu, p, 4);
        bj[j] = p;
    }

    float* Bp = g_b + ((size_t)b * ICAPS + i) * NCAPS;
    if (addPrev) {
        float bp0 = Bp[dq], bp1 = Bp[dq + 8];
        #pragma unroll
        for (int j = 0; j < NCAPS; ++j) {
            float src = (j < 8) ? bp0 : bp1;
            bj[j] += __shfl_sync(0xffffffffu, src, (lane & 24) | (j & 7));
        }
    } else {
        float b0 = 0.f, b1 = 0.f;
        #pragma unroll
        for (int j = 0; j < 8; ++j)  b0 = (dq == j) ? bj[j] : b0;
        #pragma unroll
        for (int j = 8; j < 16; ++j) b1 = (dq == j - 8) ? bj[j] : b1;
        Bp[dq] = b0;
        Bp[dq + 8] = b1;
    }

    // softmax over j
    float m = bj[0];
    #pragma unroll
    for (int j = 1; j < NCAPS; ++j) m = fmaxf(m, bj[j]);
    float sum = 0.f;
    #pragma unroll
    for (int j = 0; j < NCAPS; ++j) { bj[j] = __expf(bj[j] - m); sum += bj[j]; }
    const float inv = 1.f / sum;

    // pass 2: weighted sum, two j-halves to cap register pressure
    #pragma unroll
    for (int h = 0; h < 2; ++h) {
        float4 sacc[8];
        #pragma unroll
        for (int jj = 0; jj < 8; ++jj) sacc[jj] = make_float4(0.f, 0.f, 0.f, 0.f);
        #pragma unroll
        for (int jj = 0; jj < 8; ++jj) {
            const int j = h * 8 + jj;
            float4 u = ldg4_nc(U + j * 8 + dq);   // L1 hit; not CSE-able
            float cc = bj[j] * inv;
            sacc[jj].x = fmaf(cc, u.x, sacc[jj].x);
            sacc[jj].y = fmaf(cc, u.y, sacc[jj].y);
            sacc[jj].z = fmaf(cc, u.z, sacc[jj].z);
            sacc[jj].w = fmaf(cc, u.w, sacc[jj].w);
        }
        #pragma unroll
        for (int jj = 0; jj < 8; ++jj) {
            sacc[jj].x += __shfl_xor_sync(0xffffffffu, sacc[jj].x, 8);
            sacc[jj].x += __shfl_xor_sync(0xffffffffu, sacc[jj].x, 16);
            sacc[jj].y += __shfl_xor_sync(0xffffffffu, sacc[jj].y, 8);
            sacc[jj].y += __shfl_xor_sync(0xffffffffu, sacc[jj].y, 16);
            sacc[jj].z += __shfl_xor_sync(0xffffffffu, sacc[jj].z, 8);
            sacc[jj].z += __shfl_xor_sync(0xffffffffu, sacc[jj].z, 16);
            sacc[jj].w += __shfl_xor_sync(0xffffffffu, sacc[jj].w, 8);
            sacc[jj].w += __shfl_xor_sync(0xffffffffu, sacc[jj].w, 16);
        }
        if (seg == 0) {
            #pragma unroll
            for (int jj = 0; jj < 8; ++jj)
                *reinterpret_cast<float4*>(&smr[wid][h * 8 + jj][dq * 4]) = sacc[jj];
        }
    }
    __syncthreads();
    for (int q = threadIdx.x; q < 512; q += 256) {
        int j = q >> 5, d = q & 31;
        float s = 0.f;
        #pragma unroll
        for (int w = 0; w < 8; ++w) s += smr[w][j][d];
        g_part[((size_t)chunk * B_ + b) * 512 + q] = s;
    }
}

// ---------------------------------------------------------------------------
// K4: reduce 16 chunks, squash, write g_v or final out. grid B_, 512 thr.
// ---------------------------------------------------------------------------
__global__ void __launch_bounds__(512)
squash_reduce(float* __restrict__ out, int final_iter) {
    const int b = blockIdx.x, tid = threadIdx.x;
    float s = 0.f;
    #pragma unroll
    for (int c = 0; c < 16; ++c)
        s += g_part[((size_t)c * B_ + b) * 512 + tid];
    float ss = s * s;
    #pragma unroll
    for (int o = 16; o; o >>= 1) ss += __shfl_xor_sync(0xffffffffu, ss, o);
    float scale = ss / (1.f + ss) * rsqrtf(ss + 1e-7f);
    float* dst = final_iter ? out : g_v;
    dst[(size_t)b * 512 + tid] = scale * s;
}

// ---------------------------------------------------------------------------
extern "C" void kernel_launch(void* const* d_in, const int* in_sizes, int n_in,
                              void* d_out, int out_size) {
    const float* x = (const float*)d_in[0];
    const float* W = (const float*)d_in[1];
    float* out = (float*)d_out;

    cudaFuncSetAttribute(uhat_mma, cudaFuncAttributeMaxDynamicSharedMemorySize,
                         SMEM_BYTES);

    uhat_mma<<<ICAPS, 256, SMEM_BYTES>>>(x, W);

    s_uniform_part<<<dim3(B_, 16), 512>>>();  // r=0 partials
    squash_reduce<<<B_, 512>>>(out, 0);       // -> v
    fused_route<<<dim3(B_, 16), 256>>>(0);    // r=1
    squash_reduce<<<B_, 512>>>(out, 0);       // -> v
    fused_route<<<dim3(B_, 16), 256>>>(1);    // r=2
    squash_reduce<<<B_, 512>>>(out, 1);       // -> out
}

// round 15
// speedup vs baseline: 4.0099x; 1.0900x over previous
#include <cuda_runtime.h>
#include <cuda_fp16.h>
#include <cstdint>

// CapsuleLayer dynamic routing.
//   inputs: (64, 512, 128) fp32 ; W: (512, 16, 128, 32) fp32 ; num_routing=3
//   out: (64, 16, 32) fp32
//
// K1 uhat_mma      : mma.sync m16n8k16 fp16 split precision, 2 groups:
//                    u_hat = (Ah+Al)*Bh. (HMMA floor ~33-38us; unchanged)
// K2 s_uniform_part: r=0 weighted-sum partials (c = 1/16), float4, 16 chunks.
// K3 fused_route   : v4 -- phase A: dots+softmax -> c in smem;
//                    phase B: (j,d)-threads weighted sum, no shuffles.
// K4 squash_reduce : reduce 16 chunk partials + squash -> v or final out.

#define B_    64
#define ICAPS 512
#define IDIM  128
#define NCAPS 16
#define ODIM  32

__device__ float g_uhat[(size_t)B_ * ICAPS * NCAPS * ODIM];  // 67 MB
__device__ float g_b[(size_t)B_ * ICAPS * NCAPS];
__device__ float g_v[(size_t)B_ * NCAPS * ODIM];
__device__ float g_part[(size_t)16 * B_ * NCAPS * ODIM];     // 2 MB

// ---------------- helpers ----------------
__device__ __forceinline__ uint32_t pack_f16(float v0, float v1) {
    uint32_t r;
    asm("cvt.rn.f16x2.f32 %0, %1, %2;" : "=r"(r) : "f"(v1), "f"(v0));
    return r;
}
__device__ __forceinline__ void split2_f16(float v0, float v1,
                                           uint32_t& h, uint32_t& l) {
    asm("cvt.rn.f16x2.f32 %0, %1, %2;" : "=r"(h) : "f"(v1), "f"(v0));
    float f0, f1;
    asm("{ .reg .b16 x,y; mov.b32 {x,y}, %2; cvt.f32.f16 %0, x; cvt.f32.f16 %1, y; }"
        : "=f"(f0), "=f"(f1) : "r"(h));
    asm("cvt.rn.f16x2.f32 %0, %1, %2;" : "=r"(l) : "f"(v1 - f1), "f"(v0 - f0));
}
__device__ __forceinline__ void mma16816(float* c, const uint32_t* a,
                                         uint32_t b0, uint32_t b1) {
    asm volatile(
        "mma.sync.aligned.m16n8k16.row.col.f32.f16.f16.f32 "
        "{%0,%1,%2,%3}, {%4,%5,%6,%7}, {%8,%9}, {%0,%1,%2,%3};"
        : "+f"(c[0]), "+f"(c[1]), "+f"(c[2]), "+f"(c[3])
        : "r"(a[0]), "r"(a[1]), "r"(a[2]), "r"(a[3]), "r"(b0), "r"(b1));
}

#define XH_STRIDE 136
__device__ __forceinline__ int woff(int kb, int d, int w) {
    return (kb * 32 + d) * 36 + (w ^ (d >> 3));
}
#define WBUF_WORDS (2 * 32 * 36)
#define OFF_W      (64 * XH_STRIDE * 2 * 2)
#define SMEM_BYTES (OFF_W + 2 * WBUF_WORDS * 4)    // 53248 B

// ---------------------------------------------------------------------------
// K1: u_hat GEMM (unchanged from R13 — at fp16 2-group HMMA floor).
// ---------------------------------------------------------------------------
__global__ void __launch_bounds__(256, 2)
uhat_mma(const float* __restrict__ x, const float* __restrict__ W) {
    extern __shared__ char sm[];
    uint16_t* xh = reinterpret_cast<uint16_t*>(sm);
    uint16_t* xl = xh + 64 * XH_STRIDE;
    uint32_t* wb0 = reinterpret_cast<uint32_t*>(sm + OFF_W);
    uint32_t* wb1 = wb0 + WBUF_WORDS;

    const int i = blockIdx.x, tid = threadIdx.x;
    const int wid = tid >> 5, lane = tid & 31;
    const float* Wi = W + (size_t)i * NCAPS * IDIM * ODIM;

    float p0[8], p1[8];
    auto prefetchW = [&](int j) {
        const float* Wj = Wi + (size_t)j * IDIM * ODIM;
        #pragma unroll
        for (int r = 0; r < 8; ++r) {
            int q = r * 256 + tid;
            int d = q & 31, kp = q >> 5;
            const float* p = Wj + (2 * kp) * ODIM + d;
            p0[r] = __ldcs(p);
            p1[r] = __ldcs(p + ODIM);
        }
    };
    auto convertW = [&](uint32_t* wb) {
        #pragma unroll
        for (int r = 0; r < 8; ++r) {
            int q = r * 256 + tid;
            int d = q & 31, kp = q >> 5;
            int kb = kp >> 5, w = kp & 31;
            wb[woff(kb, d, w)] = pack_f16(p0[r], p1[r]);
        }
    };

    prefetchW(0);
    for (int q = tid; q < 2048; q += 256) {
        int b = q >> 5, k4 = q & 31;
        float4 v = __ldcs(reinterpret_cast<const float4*>(
                              x + ((size_t)b * ICAPS + i) * IDIM) + k4);
        uint32_t h0, l0, h1, l1;
        split2_f16(v.x, v.y, h0, l0);
        split2_f16(v.z, v.w, h1, l1);
        *reinterpret_cast<uint2*>(xh + b * XH_STRIDE + k4 * 4) = make_uint2(h0, h1);
        *reinterpret_cast<uint2*>(xl + b * XH_STRIDE + k4 * 4) = make_uint2(l0, l1);
    }
    convertW(wb0);
    __syncthreads();

    const int mt = wid & 3, nh = wid >> 2;
    const int m0 = mt * 16;
    uint32_t A[8][2][4];
    {
        const int r0 = m0 + (lane >> 2);
        const int cb = (lane & 3) * 2;
        #pragma unroll
        for (int ks = 0; ks < 8; ++ks) {
            int c0 = ks * 16 + cb;
            A[ks][0][0] = *reinterpret_cast<const uint32_t*>(xh + r0 * XH_STRIDE + c0);
            A[ks][0][1] = *reinterpret_cast<const uint32_t*>(xh + (r0 + 8) * XH_STRIDE + c0);
            A[ks][0][2] = *reinterpret_cast<const uint32_t*>(xh + r0 * XH_STRIDE + c0 + 8);
            A[ks][0][3] = *reinterpret_cast<const uint32_t*>(xh + (r0 + 8) * XH_STRIDE + c0 + 8);
            A[ks][1][0] = *reinterpret_cast<const uint32_t*>(xl + r0 * XH_STRIDE + c0);
            A[ks][1][1] = *reinterpret_cast<const uint32_t*>(xl + (r0 + 8) * XH_STRIDE + c0);
            A[ks][1][2] = *reinterpret_cast<const uint32_t*>(xl + r0 * XH_STRIDE + c0 + 8);
            A[ks][1][3] = *reinterpret_cast<const uint32_t*>(xl + (r0 + 8) * XH_STRIDE + c0 + 8);
        }
    }

    const int lw = lane & 3;
    const int dq = lane >> 2;

    for (int j = 0; j < 16; ++j) {
        uint32_t* wcur = (j & 1) ? wb1 : wb0;
        uint32_t* wnxt = (j & 1) ? wb0 : wb1;
        if (j < 15) prefetchW(j + 1);

        float c[2][4] = {{0.f, 0.f, 0.f, 0.f}, {0.f, 0.f, 0.f, 0.f}};
        #pragma unroll
        for (int ks = 0; ks < 8; ++ks) {
            const int kb = ks >> 2;
            const int w0 = 8 * (ks & 3) + lw;
            #pragma unroll
            for (int nt = 0; nt < 2; ++nt) {
                const int d = nh * 16 + nt * 8 + dq;
                uint32_t bh0 = wcur[woff(kb, d, w0)];
                uint32_t bh1 = wcur[woff(kb, d, w0 + 4)];
                mma16816(c[nt], A[ks][0], bh0, bh1);
                mma16816(c[nt], A[ks][1], bh0, bh1);
            }
        }

        const int brow = m0 + (lane >> 2);
        const int dc0 = nh * 16 + (lane & 3) * 2;
        #pragma unroll
        for (int nt = 0; nt < 2; ++nt) {
            int d = dc0 + nt * 8;
            *reinterpret_cast<float2*>(
                g_uhat + ((((size_t)brow * ICAPS + i) * NCAPS + j) * ODIM + d)) =
                make_float2(c[nt][0], c[nt][1]);
            *reinterpret_cast<float2*>(
                g_uhat + ((((size_t)(brow + 8) * ICAPS + i) * NCAPS + j) * ODIM + d)) =
                make_float2(c[nt][2], c[nt][3]);
        }

        if (j < 15) convertW(wnxt);
        __syncthreads();
    }
}

// ---------------------------------------------------------------------------
// K2: r=0 partials, c = 1/16. grid (B_, 16): 32 i/chunk. 512 thr.
// ---------------------------------------------------------------------------
__global__ void __launch_bounds__(512)
s_uniform_part() {
    const int b = blockIdx.x, chunk = blockIdx.y, tid = threadIdx.x;
    const int ig = tid >> 7, f = tid & 127;
    const float4* U = reinterpret_cast<const float4*>(
                          g_uhat + ((size_t)b * ICAPS + chunk * 32) * 512) + f;
    float4 acc = make_float4(0.f, 0.f, 0.f, 0.f);
    #pragma unroll 4
    for (int ii = 0; ii < 8; ++ii) {
        float4 u = U[(size_t)(ii * 4 + ig) * 128];
        acc.x += u.x; acc.y += u.y; acc.z += u.z; acc.w += u.w;
    }
    __shared__ float4 smr[4][128];
    smr[ig][f] = acc;
    __syncthreads();
    if (tid < 128) {
        float4 a = smr[0][tid], s;
        s.x = (a.x + smr[1][tid].x + smr[2][tid].x + smr[3][tid].x) * 0.0625f;
        s.y = (a.y + smr[1][tid].y + smr[2][tid].y + smr[3][tid].y) * 0.0625f;
        s.z = (a.z + smr[1][tid].z + smr[2][tid].z + smr[3][tid].z) * 0.0625f;
        s.w = (a.w + smr[1][tid].w + smr[2][tid].w + smr[3][tid].w) * 0.0625f;
        reinterpret_cast<float4*>(
            g_part + ((size_t)chunk * B_ + b) * 512)[tid] = s;
    }
}

// ---------------------------------------------------------------------------
// K3: fused routing v4. grid (B_, 16), 256 thr.
// Phase A: warp = 4 i (8-lane segments): dots -> bias -> softmax -> csh.
// Phase B: thread = float2 of (j,d); weighted sum over 32 i; no shuffles.
// ---------------------------------------------------------------------------
#define CSTRIDE 24   // csh row stride: conflict-free for 4-seg x 8-lane writes
__global__ void __launch_bounds__(256)
fused_route(int addPrev) {
    const int b = blockIdx.x, chunk = blockIdx.y;
    const int wid = threadIdx.x >> 5, lane = threadIdx.x & 31;
    const int seg = lane >> 3, dq = lane & 7;

    __shared__ float vsh[512];                 // 2 KB
    __shared__ float csh[32 * CSTRIDE];        // 3 KB
    for (int q = threadIdx.x; q < 512; q += 256)
        vsh[q] = g_v[(size_t)b * 512 + q];
    __syncthreads();

    const int il = wid * 4 + seg;              // local i (0..31)
    const int i = chunk * 32 + il;
    const float4* U = reinterpret_cast<const float4*>(
                          g_uhat + ((size_t)b * ICAPS + i) * 512);

    // ---- phase A: agreement dots ----
    float bj[NCAPS];
    #pragma unroll
    for (int j = 0; j < NCAPS; ++j) {
        float4 u = U[j * 8 + dq];
        const float4 vj = *reinterpret_cast<const float4*>(&vsh[j * 32 + dq * 4]);
        float p = u.x * vj.x + u.y * vj.y + u.z * vj.z + u.w * vj.w;
        p += __shfl_xor_sync(0xffffffffu, p, 1);
        p += __shfl_xor_sync(0xffffffffu, p, 2);
        p += __shfl_xor_sync(0xffffffffu, p, 4);
        bj[j] = p;
    }

    float* Bp = g_b + ((size_t)b * ICAPS + i) * NCAPS;
    if (addPrev) {
        float bp0 = Bp[dq], bp1 = Bp[dq + 8];
        #pragma unroll
        for (int j = 0; j < NCAPS; ++j) {
            float src = (j < 8) ? bp0 : bp1;
            bj[j] += __shfl_sync(0xffffffffu, src, (lane & 24) | (j & 7));
        }
    } else {
        float b0 = 0.f, b1 = 0.f;
        #pragma unroll
        for (int j = 0; j < 8; ++j)  b0 = (dq == j) ? bj[j] : b0;
        #pragma unroll
        for (int j = 8; j < 16; ++j) b1 = (dq == j - 8) ? bj[j] : b1;
        Bp[dq] = b0;
        Bp[dq + 8] = b1;
    }

    // softmax over j -> coupling coeffs into csh
    float m = bj[0];
    #pragma unroll
    for (int j = 1; j < NCAPS; ++j) m = fmaxf(m, bj[j]);
    float sum = 0.f;
    #pragma unroll
    for (int j = 0; j < NCAPS; ++j) { bj[j] = __expf(bj[j] - m); sum += bj[j]; }
    const float inv = 1.f / sum;
    {
        float c0 = 0.f, c1 = 0.f;
        #pragma unroll
        for (int j = 0; j < 8; ++j)  c0 = (dq == j) ? bj[j] : c0;
        #pragma unroll
        for (int j = 8; j < 16; ++j) c1 = (dq == j - 8) ? bj[j] : c1;
        csh[il * CSTRIDE + dq]     = c0 * inv;
        csh[il * CSTRIDE + dq + 8] = c1 * inv;
    }
    __syncthreads();

    // ---- phase B: weighted sum, thread = float2 of (j,d) ----
    const int q2 = threadIdx.x;          // float2 index (0..255)
    const int jB = q2 >> 4;              // j = (2*q2)/32
    const float2* Ub = reinterpret_cast<const float2*>(
                           g_uhat + ((size_t)b * ICAPS + chunk * 32) * 512) + q2;
    float2 acc = make_float2(0.f, 0.f);
    #pragma unroll 8
    for (int ii = 0; ii < 32; ++ii) {
        float cc = csh[ii * CSTRIDE + jB];
        float2 u = Ub[ii * 256];
        acc.x = fmaf(cc, u.x, acc.x);
        acc.y = fmaf(cc, u.y, acc.y);
    }
    reinterpret_cast<float2*>(
        g_part + ((size_t)chunk * B_ + b) * 512)[q2] = acc;
}

// ---------------------------------------------------------------------------
// K4: reduce 16 chunks, squash, write g_v or final out. grid B_, 512 thr.
// ---------------------------------------------------------------------------
__global__ void __launch_bounds__(512)
squash_reduce(float* __restrict__ out, int final_iter) {
    const int b = blockIdx.x, tid = threadIdx.x;
    float s = 0.f;
    #pragma unroll
    for (int c = 0; c < 16; ++c)
        s += g_part[((size_t)c * B_ + b) * 512 + tid];
    float ss = s * s;
    #pragma unroll
    for (int o = 16; o; o >>= 1) ss += __shfl_xor_sync(0xffffffffu, ss, o);
    float scale = ss / (1.f + ss) * rsqrtf(ss + 1e-7f);
    float* dst = final_iter ? out : g_v;
    dst[(size_t)b * 512 + tid] = scale * s;
}

// ---------------------------------------------------------------------------
extern "C" void kernel_launch(void* const* d_in, const int* in_sizes, int n_in,
                              void* d_out, int out_size) {
    const float* x = (const float*)d_in[0];
    const float* W = (const float*)d_in[1];
    float* out = (float*)d_out;

    cudaFuncSetAttribute(uhat_mma, cudaFuncAttributeMaxDynamicSharedMemorySize,
                         SMEM_BYTES);

    uhat_mma<<<ICAPS, 256, SMEM_BYTES>>>(x, W);

    s_uniform_part<<<dim3(B_, 16), 512>>>();  // r=0 partials
    squash_reduce<<<B_, 512>>>(out, 0);       // -> v
    fused_route<<<dim3(B_, 16), 256>>>(0);    // r=1
    squash_reduce<<<B_, 512>>>(out, 0);       // -> v
    fused_route<<<dim3(B_, 16), 256>>>(1);    // r=2
    squash_reduce<<<B_, 512>>>(out, 1);       // -> out
}

// round 16
// speedup vs baseline: 4.0923x; 1.0205x over previous
#include <cuda_runtime.h>
#include <cuda_fp16.h>
#include <cstdint>

// CapsuleLayer dynamic routing.
//   inputs: (64, 512, 128) fp32 ; W: (512, 16, 128, 32) fp32 ; num_routing=3
//   out: (64, 16, 32) fp32
//
// K1 uhat_mma      : mma.sync m16n8k16 fp16 SINGLE group u_hat = Ah*Bh
//                    (rn-rounded fp16 x and W; dropped residual terms ~4e-4).
// K2 s_uniform_part: r=0 weighted-sum partials (c = 1/16) -> g_part buf0.
// K3 fused_route   : phase 0: reduce partials + squash -> v (in smem);
//                    phase A: dots + bias + softmax -> c; phase B: partials.
//                    g_part ping-pong: route(0) buf0->buf1, route(1) buf1->buf0.
// K4 squash_final  : reduce buf0 partials + squash -> out.

#define B_    64
#define ICAPS 512
#define IDIM  128
#define NCAPS 16
#define ODIM  32

__device__ float g_uhat[(size_t)B_ * ICAPS * NCAPS * ODIM];      // 67 MB
__device__ float g_b[(size_t)B_ * ICAPS * NCAPS];
__device__ float g_part[(size_t)2 * 16 * B_ * NCAPS * ODIM];     // 2 x 2 MB

__device__ __forceinline__ float* GP(int buf) {
    return g_part + (size_t)buf * 16 * B_ * 512;
}

// ---------------- helpers ----------------
__device__ __forceinline__ uint32_t pack_f16(float v0, float v1) {
    uint32_t r;
    asm("cvt.rn.f16x2.f32 %0, %1, %2;" : "=r"(r) : "f"(v1), "f"(v0));
    return r;
}
__device__ __forceinline__ void mma16816(float* c, const uint32_t* a,
                                         uint32_t b0, uint32_t b1) {
    asm volatile(
        "mma.sync.aligned.m16n8k16.row.col.f32.f16.f16.f32 "
        "{%0,%1,%2,%3}, {%4,%5,%6,%7}, {%8,%9}, {%0,%1,%2,%3};"
        : "+f"(c[0]), "+f"(c[1]), "+f"(c[2]), "+f"(c[3])
        : "r"(a[0]), "r"(a[1]), "r"(a[2]), "r"(a[3]), "r"(b0), "r"(b1));
}

#define XH_STRIDE 136
__device__ __forceinline__ int woff(int kb, int d, int w) {
    return (kb * 32 + d) * 36 + (w ^ (d >> 3));
}
#define WBUF_WORDS (2 * 32 * 36)                 // 9216 B per buffer
#define OFF_W      (64 * XH_STRIDE * 2)          // 17408 B (x hi only)
#define SMEM_BYTES (OFF_W + 2 * WBUF_WORDS * 4)  // 35840 B

// ---------------------------------------------------------------------------
// K1: u_hat GEMM, single fp16 group. One block per i; 8 warps =
// (m-tile 0..3) x (n-half 0..1); 16 j-phases, W double-buffered via regs.
// ---------------------------------------------------------------------------
__global__ void __launch_bounds__(256, 2)
uhat_mma(const float* __restrict__ x, const float* __restrict__ W) {
    extern __shared__ char sm[];
    uint16_t* xh = reinterpret_cast<uint16_t*>(sm);
    uint32_t* wb0 = reinterpret_cast<uint32_t*>(sm + OFF_W);
    uint32_t* wb1 = wb0 + WBUF_WORDS;

    const int i = blockIdx.x, tid = threadIdx.x;
    const int wid = tid >> 5, lane = tid & 31;
    const float* Wi = W + (size_t)i * NCAPS * IDIM * ODIM;

    float p0[8], p1[8];
    auto prefetchW = [&](int j) {
        const float* Wj = Wi + (size_t)j * IDIM * ODIM;
        #pragma unroll
        for (int r = 0; r < 8; ++r) {
            int q = r * 256 + tid;
            int d = q & 31, kp = q >> 5;
            const float* p = Wj + (2 * kp) * ODIM + d;
            p0[r] = __ldcs(p);
            p1[r] = __ldcs(p + ODIM);
        }
    };
    auto convertW = [&](uint32_t* wb) {
        #pragma unroll
        for (int r = 0; r < 8; ++r) {
            int q = r * 256 + tid;
            int d = q & 31, kp = q >> 5;
            int kb = kp >> 5, w = kp & 31;
            wb[woff(kb, d, w)] = pack_f16(p0[r], p1[r]);
        }
    };

    prefetchW(0);
    // stage x[:, i, :] as fp16 (rn), rows b, k contiguous
    for (int q = tid; q < 2048; q += 256) {
        int b = q >> 5, k4 = q & 31;
        float4 v = __ldcs(reinterpret_cast<const float4*>(
                              x + ((size_t)b * ICAPS + i) * IDIM) + k4);
        uint32_t h0 = pack_f16(v.x, v.y), h1 = pack_f16(v.z, v.w);
        *reinterpret_cast<uint2*>(xh + b * XH_STRIDE + k4 * 4) = make_uint2(h0, h1);
    }
    convertW(wb0);
    __syncthreads();

    const int mt = wid & 3, nh = wid >> 2;
    const int m0 = mt * 16;
    uint32_t A[8][4];
    {
        const int r0 = m0 + (lane >> 2);
        const int cb = (lane & 3) * 2;
        #pragma unroll
        for (int ks = 0; ks < 8; ++ks) {
            int c0 = ks * 16 + cb;
            A[ks][0] = *reinterpret_cast<const uint32_t*>(xh + r0 * XH_STRIDE + c0);
            A[ks][1] = *reinterpret_cast<const uint32_t*>(xh + (r0 + 8) * XH_STRIDE + c0);
            A[ks][2] = *reinterpret_cast<const uint32_t*>(xh + r0 * XH_STRIDE + c0 + 8);
            A[ks][3] = *reinterpret_cast<const uint32_t*>(xh + (r0 + 8) * XH_STRIDE + c0 + 8);
        }
    }

    const int lw = lane & 3;
    const int dq = lane >> 2;

    for (int j = 0; j < 16; ++j) {
        uint32_t* wcur = (j & 1) ? wb1 : wb0;
        uint32_t* wnxt = (j & 1) ? wb0 : wb1;
        if (j < 15) prefetchW(j + 1);

        float c[2][4] = {{0.f, 0.f, 0.f, 0.f}, {0.f, 0.f, 0.f, 0.f}};
        #pragma unroll
        for (int ks = 0; ks < 8; ++ks) {
            const int kb = ks >> 2;
            const int w0 = 8 * (ks & 3) + lw;
            #pragma unroll
            for (int nt = 0; nt < 2; ++nt) {
                const int d = nh * 16 + nt * 8 + dq;
                uint32_t bh0 = wcur[woff(kb, d, w0)];
                uint32_t bh1 = wcur[woff(kb, d, w0 + 4)];
                mma16816(c[nt], A[ks], bh0, bh1);
            }
        }

        const int brow = m0 + (lane >> 2);
        const int dc0 = nh * 16 + (lane & 3) * 2;
        #pragma unroll
        for (int nt = 0; nt < 2; ++nt) {
            int d = dc0 + nt * 8;
            *reinterpret_cast<float2*>(
                g_uhat + ((((size_t)brow * ICAPS + i) * NCAPS + j) * ODIM + d)) =
                make_float2(c[nt][0], c[nt][1]);
            *reinterpret_cast<float2*>(
                g_uhat + ((((size_t)(brow + 8) * ICAPS + i) * NCAPS + j) * ODIM + d)) =
                make_float2(c[nt][2], c[nt][3]);
        }

        if (j < 15) convertW(wnxt);
        __syncthreads();
    }
}

// ---------------------------------------------------------------------------
// K2: r=0 partials, c = 1/16, into GP(0). grid (B_, 16): 32 i/chunk, 512 thr.
// ---------------------------------------------------------------------------
__global__ void __launch_bounds__(512)
s_uniform_part() {
    const int b = blockIdx.x, chunk = blockIdx.y, tid = threadIdx.x;
    const int ig = tid >> 7, f = tid & 127;
    const float4* U = reinterpret_cast<const float4*>(
                          g_uhat + ((size_t)b * ICAPS + chunk * 32) * 512) + f;
    float4 acc = make_float4(0.f, 0.f, 0.f, 0.f);
    #pragma unroll 4
    for (int ii = 0; ii < 8; ++ii) {
        float4 u = U[(size_t)(ii * 4 + ig) * 128];
        acc.x += u.x; acc.y += u.y; acc.z += u.z; acc.w += u.w;
    }
    __shared__ float4 smr[4][128];
    smr[ig][f] = acc;
    __syncthreads();
    if (tid < 128) {
        float4 a = smr[0][tid], s;
        s.x = (a.x + smr[1][tid].x + smr[2][tid].x + smr[3][tid].x) * 0.0625f;
        s.y = (a.y + smr[1][tid].y + smr[2][tid].y + smr[3][tid].y) * 0.0625f;
        s.z = (a.z + smr[1][tid].z + smr[2][tid].z + smr[3][tid].z) * 0.0625f;
        s.w = (a.w + smr[1][tid].w + smr[2][tid].w + smr[3][tid].w) * 0.0625f;
        reinterpret_cast<float4*>(
            GP(0) + ((size_t)chunk * B_ + b) * 512)[tid] = s;
    }
}

// ---------------------------------------------------------------------------
// K3: fused routing. grid (B_, 16), 256 thr.
// Phase 0: reduce src partials + squash -> vsh (identical in every block).
// Phase A: warp = 4 i (8-lane segments): dots -> bias -> softmax -> csh.
// Phase B: thread = float2 of (j,d); weighted sum over 32 i -> dst partials.
// ---------------------------------------------------------------------------
#define CSTRIDE 24
__global__ void __launch_bounds__(256)
fused_route(int addPrev, int srcBuf) {
    const int b = blockIdx.x, chunk = blockIdx.y;
    const int wid = threadIdx.x >> 5, lane = threadIdx.x & 31;
    const int seg = lane >> 3, dq = lane & 7;
    const int q = threadIdx.x;                  // float2 index (0..255)

    __shared__ float vsh[512];                  // 2 KB
    __shared__ float csh[32 * CSTRIDE];         // 3 KB

    // ---- phase 0: v = squash(sum of 16 partial chunks) ----
    {
        const float2* gp = reinterpret_cast<const float2*>(GP(srcBuf)) + b * 256 + q;
        float2 s = make_float2(0.f, 0.f);
        #pragma unroll
        for (int c = 0; c < 16; ++c) {
            float2 p = gp[(size_t)c * B_ * 256];
            s.x += p.x; s.y += p.y;
        }
        float ss = fmaf(s.x, s.x, s.y * s.y);
        ss += __shfl_xor_sync(0xffffffffu, ss, 1);
        ss += __shfl_xor_sync(0xffffffffu, ss, 2);
        ss += __shfl_xor_sync(0xffffffffu, ss, 4);
        ss += __shfl_xor_sync(0xffffffffu, ss, 8);   // 16 lanes = one j
        float scale = ss / (1.f + ss) * rsqrtf(ss + 1e-7f);
        vsh[2 * q]     = scale * s.x;
        vsh[2 * q + 1] = scale * s.y;
    }
    __syncthreads();

    const int il = wid * 4 + seg;               // local i (0..31)
    const int i = chunk * 32 + il;
    const float4* U = reinterpret_cast<const float4*>(
                          g_uhat + ((size_t)b * ICAPS + i) * 512);

    // ---- phase A: agreement dots ----
    float bj[NCAPS];
    #pragma unroll
    for (int j = 0; j < NCAPS; ++j) {
        float4 u = U[j * 8 + dq];
        const float4 vj = *reinterpret_cast<const float4*>(&vsh[j * 32 + dq * 4]);
        float p = u.x * vj.x + u.y * vj.y + u.z * vj.z + u.w * vj.w;
        p += __shfl_xor_sync(0xffffffffu, p, 1);
        p += __shfl_xor_sync(0xffffffffu, p, 2);
        p += __shfl_xor_sync(0xffffffffu, p, 4);
        bj[j] = p;
    }

    float* Bp = g_b + ((size_t)b * ICAPS + i) * NCAPS;
    if (addPrev) {
        float bp0 = Bp[dq], bp1 = Bp[dq + 8];
        #pragma unroll
        for (int j = 0; j < NCAPS; ++j) {
            float src = (j < 8) ? bp0 : bp1;
            bj[j] += __shfl_sync(0xffffffffu, src, (lane & 24) | (j & 7));
        }
    } else {
        float b0 = 0.f, b1 = 0.f;
        #pragma unroll
        for (int j = 0; j < 8; ++j)  b0 = (dq == j) ? bj[j] : b0;
        #pragma unroll
        for (int j = 8; j < 16; ++j) b1 = (dq == j - 8) ? bj[j] : b1;
        Bp[dq] = b0;
        Bp[dq + 8] = b1;
    }

    // softmax over j -> coupling coeffs into csh
    float m = bj[0];
    #pragma unroll
    for (int j = 1; j < NCAPS; ++j) m = fmaxf(m, bj[j]);
    float sum = 0.f;
    #pragma unroll
    for (int j = 0; j < NCAPS; ++j) { bj[j] = __expf(bj[j] - m); sum += bj[j]; }
    const float inv = 1.f / sum;
    {
        float c0 = 0.f, c1 = 0.f;
        #pragma unroll
        for (int j = 0; j < 8; ++j)  c0 = (dq == j) ? bj[j] : c0;
        #pragma unroll
        for (int j = 8; j < 16; ++j) c1 = (dq == j - 8) ? bj[j] : c1;
        csh[il * CSTRIDE + dq]     = c0 * inv;
        csh[il * CSTRIDE + dq + 8] = c1 * inv;
    }
    __syncthreads();

    // ---- phase B: weighted sum, thread = float2 of (j,d) ----
    const int jB = q >> 4;
    const float2* Ub = reinterpret_cast<const float2*>(
                           g_uhat + ((size_t)b * ICAPS + chunk * 32) * 512) + q;
    float2 acc = make_float2(0.f, 0.f);
    #pragma unroll 8
    for (int ii = 0; ii < 32; ++ii) {
        float cc = csh[ii * CSTRIDE + jB];
        float2 u = Ub[ii * 256];
        acc.x = fmaf(cc, u.x, acc.x);
        acc.y = fmaf(cc, u.y, acc.y);
    }
    reinterpret_cast<float2*>(
        GP(srcBuf ^ 1) + ((size_t)chunk * B_ + b) * 512)[q] = acc;
}

// ---------------------------------------------------------------------------
// K4: final reduce of GP(0) + squash -> out. grid B_, 512 thr.
// ---------------------------------------------------------------------------
__global__ void __launch_bounds__(512)
squash_final(float* __restrict__ out) {
    const int b = blockIdx.x, tid = threadIdx.x;
    float s = 0.f;
    #pragma unroll
    for (int c = 0; c < 16; ++c)
        s += GP(0)[((size_t)c * B_ + b) * 512 + tid];
    float ss = s * s;
    #pragma unroll
    for (int o = 16; o; o >>= 1) ss += __shfl_xor_sync(0xffffffffu, ss, o);
    float scale = ss / (1.f + ss) * rsqrtf(ss + 1e-7f);
    out[(size_t)b * 512 + tid] = scale * s;
}

// ---------------------------------------------------------------------------
extern "C" void kernel_launch(void* const* d_in, const int* in_sizes, int n_in,
                              void* d_out, int out_size) {
    const float* x = (const float*)d_in[0];
    const float* W = (const float*)d_in[1];
    float* out = (float*)d_out;

    cudaFuncSetAttribute(uhat_mma, cudaFuncAttributeMaxDynamicSharedMemorySize,
                         SMEM_BYTES);

    uhat_mma<<<ICAPS, 256, SMEM_BYTES>>>(x, W);

    s_uniform_part<<<dim3(B_, 16), 512>>>();        // r=0 partials -> buf0
    fused_route<<<dim3(B_, 16), 256>>>(0, 0);       // r=1: v from buf0 -> buf1
    fused_route<<<dim3(B_, 16), 256>>>(1, 1);       // r=2: v from buf1 -> buf0
    squash_final<<<B_, 512>>>(out);                 // out from buf0
}

// round 17
// speedup vs baseline: 4.3261x; 1.0571x over previous
#include <cuda_runtime.h>
#include <cuda_fp16.h>
#include <cstdint>

// CapsuleLayer dynamic routing.
//   inputs: (64, 512, 128) fp32 ; W: (512, 16, 128, 32) fp32 ; num_routing=3
//   out: (64, 16, 32) fp32
//
// u_hat stored in fp16 (33.5 MB): halves all routing DRAM traffic.
// All accumulation fp32; only storage quantized (adds ~3e-4, total ~5e-4).
//
// K1 uhat_mma      : mma.sync m16n8k16 fp16 single group u_hat = Ah*Bh.
// K2 s_uniform_part: r=0 weighted-sum partials (c = 1/16) -> g_part.
// K3 squash_reduce : reduce 16 chunk partials + squash -> g_v or out.
// K4 fused_route   : dots + bias + softmax -> c (smem); weighted-sum partials.

#define B_    64
#define ICAPS 512
#define IDIM  128
#define NCAPS 16
#define ODIM  32

__device__ uint16_t g_uhat[(size_t)B_ * ICAPS * NCAPS * ODIM];   // 33.5 MB (fp16)
__device__ float g_b[(size_t)B_ * ICAPS * NCAPS];
__device__ float g_v[(size_t)B_ * NCAPS * ODIM];
__device__ float g_part[(size_t)16 * B_ * NCAPS * ODIM];         // 2 MB

// ---------------- helpers ----------------
__device__ __forceinline__ uint32_t pack_f16(float v0, float v1) {
    uint32_t r;
    asm("cvt.rn.f16x2.f32 %0, %1, %2;" : "=r"(r) : "f"(v1), "f"(v0));
    return r;
}
__device__ __forceinline__ float2 unpack_f16(uint32_t h) {
    float f0, f1;
    asm("{ .reg .b16 x,y; mov.b32 {x,y}, %2; cvt.f32.f16 %0, x; cvt.f32.f16 %1, y; }"
        : "=f"(f0), "=f"(f1) : "r"(h));
    return make_float2(f0, f1);
}
__device__ __forceinline__ void mma16816(float* c, const uint32_t* a,
                                         uint32_t b0, uint32_t b1) {
    asm volatile(
        "mma.sync.aligned.m16n8k16.row.col.f32.f16.f16.f32 "
        "{%0,%1,%2,%3}, {%4,%5,%6,%7}, {%8,%9}, {%0,%1,%2,%3};"
        : "+f"(c[0]), "+f"(c[1]), "+f"(c[2]), "+f"(c[3])
        : "r"(a[0]), "r"(a[1]), "r"(a[2]), "r"(a[3]), "r"(b0), "r"(b1));
}

#define XH_STRIDE 136
__device__ __forceinline__ int woff(int kb, int d, int w) {
    return (kb * 32 + d) * 36 + (w ^ (d >> 3));
}
#define WBUF_WORDS (2 * 32 * 36)                 // 9216 B per buffer
#define OFF_W      (64 * XH_STRIDE * 2)          // 17408 B (x hi only)
#define SMEM_BYTES (OFF_W + 2 * WBUF_WORDS * 4)  // 35840 B

// ---------------------------------------------------------------------------
// K1: u_hat GEMM, single fp16 group, fp16 output. One block per i; 8 warps =
// (m-tile 0..3) x (n-half 0..1); 16 j-phases, W double-buffered via regs.
// ---------------------------------------------------------------------------
__global__ void __launch_bounds__(256, 2)
uhat_mma(const float* __restrict__ x, const float* __restrict__ W) {
    extern __shared__ char sm[];
    uint16_t* xh = reinterpret_cast<uint16_t*>(sm);
    uint32_t* wb0 = reinterpret_cast<uint32_t*>(sm + OFF_W);
    uint32_t* wb1 = wb0 + WBUF_WORDS;

    const int i = blockIdx.x, tid = threadIdx.x;
    const int wid = tid >> 5, lane = tid & 31;
    const float* Wi = W + (size_t)i * NCAPS * IDIM * ODIM;

    float p0[8], p1[8];
    auto prefetchW = [&](int j) {
        const float* Wj = Wi + (size_t)j * IDIM * ODIM;
        #pragma unroll
        for (int r = 0; r < 8; ++r) {
            int q = r * 256 + tid;
            int d = q & 31, kp = q >> 5;
            const float* p = Wj + (2 * kp) * ODIM + d;
            p0[r] = __ldcs(p);
            p1[r] = __ldcs(p + ODIM);
        }
    };
    auto convertW = [&](uint32_t* wb) {
        #pragma unroll
        for (int r = 0; r < 8; ++r) {
            int q = r * 256 + tid;
            int d = q & 31, kp = q >> 5;
            int kb = kp >> 5, w = kp & 31;
            wb[woff(kb, d, w)] = pack_f16(p0[r], p1[r]);
        }
    };

    prefetchW(0);
    for (int q = tid; q < 2048; q += 256) {
        int b = q >> 5, k4 = q & 31;
        float4 v = __ldcs(reinterpret_cast<const float4*>(
                              x + ((size_t)b * ICAPS + i) * IDIM) + k4);
        uint32_t h0 = pack_f16(v.x, v.y), h1 = pack_f16(v.z, v.w);
        *reinterpret_cast<uint2*>(xh + b * XH_STRIDE + k4 * 4) = make_uint2(h0, h1);
    }
    convertW(wb0);
    __syncthreads();

    const int mt = wid & 3, nh = wid >> 2;
    const int m0 = mt * 16;
    uint32_t A[8][4];
    {
        const int r0 = m0 + (lane >> 2);
        const int cb = (lane & 3) * 2;
        #pragma unroll
        for (int ks = 0; ks < 8; ++ks) {
            int c0 = ks * 16 + cb;
            A[ks][0] = *reinterpret_cast<const uint32_t*>(xh + r0 * XH_STRIDE + c0);
            A[ks][1] = *reinterpret_cast<const uint32_t*>(xh + (r0 + 8) * XH_STRIDE + c0);
            A[ks][2] = *reinterpret_cast<const uint32_t*>(xh + r0 * XH_STRIDE + c0 + 8);
            A[ks][3] = *reinterpret_cast<const uint32_t*>(xh + (r0 + 8) * XH_STRIDE + c0 + 8);
        }
    }

    const int lw = lane & 3;
    const int dq = lane >> 2;

    for (int j = 0; j < 16; ++j) {
        uint32_t* wcur = (j & 1) ? wb1 : wb0;
        uint32_t* wnxt = (j & 1) ? wb0 : wb1;
        if (j < 15) prefetchW(j + 1);

        float c[2][4] = {{0.f, 0.f, 0.f, 0.f}, {0.f, 0.f, 0.f, 0.f}};
        #pragma unroll
        for (int ks = 0; ks < 8; ++ks) {
            const int kb = ks >> 2;
            const int w0 = 8 * (ks & 3) + lw;
            #pragma unroll
            for (int nt = 0; nt < 2; ++nt) {
                const int d = nh * 16 + nt * 8 + dq;
                uint32_t bh0 = wcur[woff(kb, d, w0)];
                uint32_t bh1 = wcur[woff(kb, d, w0 + 4)];
                mma16816(c[nt], A[ks], bh0, bh1);
            }
        }

        // epilogue: fp16 output; rows = b, cols = d
        const int brow = m0 + (lane >> 2);
        const int dc0 = nh * 16 + (lane & 3) * 2;
        #pragma unroll
        for (int nt = 0; nt < 2; ++nt) {
            int d = dc0 + nt * 8;
            *reinterpret_cast<uint32_t*>(
                g_uhat + ((((size_t)brow * ICAPS + i) * NCAPS + j) * ODIM + d)) =
                pack_f16(c[nt][0], c[nt][1]);
            *reinterpret_cast<uint32_t*>(
                g_uhat + ((((size_t)(brow + 8) * ICAPS + i) * NCAPS + j) * ODIM + d)) =
                pack_f16(c[nt][2], c[nt][3]);
        }

        if (j < 15) convertW(wnxt);
        __syncthreads();
    }
}

// ---------------------------------------------------------------------------
// K2: r=0 partials, c = 1/16. grid (B_, 16): 32 i/chunk, 512 thr.
// Thread (ig, f): f indexes a uint2 (4 halves) of the 512-wide (j,d) row.
// ---------------------------------------------------------------------------
__global__ void __launch_bounds__(512)
s_uniform_part() {
    const int b = blockIdx.x, chunk = blockIdx.y, tid = threadIdx.x;
    const int ig = tid >> 7, f = tid & 127;
    const uint2* U = reinterpret_cast<const uint2*>(
                         g_uhat + ((size_t)b * ICAPS + chunk * 32) * 512) + f;
    float4 acc = make_float4(0.f, 0.f, 0.f, 0.f);
    #pragma unroll 4
    for (int ii = 0; ii < 8; ++ii) {
        uint2 uu = U[(size_t)(ii * 4 + ig) * 128];
        float2 a = unpack_f16(uu.x), c2 = unpack_f16(uu.y);
        acc.x += a.x; acc.y += a.y; acc.z += c2.x; acc.w += c2.y;
    }
    __shared__ float4 smr[4][128];
    smr[ig][f] = acc;
    __syncthreads();
    if (tid < 128) {
        float4 a = smr[0][tid], s;
        s.x = (a.x + smr[1][tid].x + smr[2][tid].x + smr[3][tid].x) * 0.0625f;
        s.y = (a.y + smr[1][tid].y + smr[2][tid].y + smr[3][tid].y) * 0.0625f;
        s.z = (a.z + smr[1][tid].z + smr[2][tid].z + smr[3][tid].z) * 0.0625f;
        s.w = (a.w + smr[1][tid].w + smr[2][tid].w + smr[3][tid].w) * 0.0625f;
        reinterpret_cast<float4*>(
            g_part + ((size_t)chunk * B_ + b) * 512)[tid] = s;
    }
}

// ---------------------------------------------------------------------------
// K3: reduce 16 chunks, squash, write g_v or final out. grid B_, 512 thr.
// ---------------------------------------------------------------------------
__global__ void __launch_bounds__(512)
squash_reduce(float* __restrict__ out, int final_iter) {
    const int b = blockIdx.x, tid = threadIdx.x;
    float s = 0.f;
    #pragma unroll
    for (int c = 0; c < 16; ++c)
        s += g_part[((size_t)c * B_ + b) * 512 + tid];
    float ss = s * s;
    #pragma unroll
    for (int o = 16; o; o >>= 1) ss += __shfl_xor_sync(0xffffffffu, ss, o);
    float scale = ss / (1.f + ss) * rsqrtf(ss + 1e-7f);
    float* dst = final_iter ? out : g_v;
    dst[(size_t)b * 512 + tid] = scale * s;
}

// ---------------------------------------------------------------------------
// K4: fused routing. grid (B_, 16), 256 thr.
// Phase A: warp = 4 i (8-lane segments): dots -> bias -> softmax -> csh.
// Phase B: thread = half2 of (j,d); weighted sum over 32 i; no shuffles.
// ---------------------------------------------------------------------------
#define CSTRIDE 24
__global__ void __launch_bounds__(256)
fused_route(int addPrev) {
    const int b = blockIdx.x, chunk = blockIdx.y;
    const int wid = threadIdx.x >> 5, lane = threadIdx.x & 31;
    const int seg = lane >> 3, dq = lane & 7;
    const int q = threadIdx.x;

    __shared__ float vsh[512];
    __shared__ float csh[32 * CSTRIDE];
    for (int p = threadIdx.x; p < 512; p += 256)
        vsh[p] = g_v[(size_t)b * 512 + p];
    __syncthreads();

    const int il = wid * 4 + seg;               // local i (0..31)
    const int i = chunk * 32 + il;
    const uint2* U = reinterpret_cast<const uint2*>(
                         g_uhat + ((size_t)b * ICAPS + i) * 512);

    // ---- phase A: agreement dots ----
    float bj[NCAPS];
    #pragma unroll
    for (int j = 0; j < NCAPS; ++j) {
        uint2 uu = U[j * 8 + dq];
        float2 a = unpack_f16(uu.x), c2 = unpack_f16(uu.y);
        const float4 vj = *reinterpret_cast<const float4*>(&vsh[j * 32 + dq * 4]);
        float p = a.x * vj.x + a.y * vj.y + c2.x * vj.z + c2.y * vj.w;
        p += __shfl_xor_sync(0xffffffffu, p, 1);
        p += __shfl_xor_sync(0xffffffffu, p, 2);
        p += __shfl_xor_sync(0xffffffffu, p, 4);
        bj[j] = p;
    }

    float* Bp = g_b + ((size_t)b * ICAPS + i) * NCAPS;
    if (addPrev) {
        float bp0 = Bp[dq], bp1 = Bp[dq + 8];
        #pragma unroll
        for (int j = 0; j < NCAPS; ++j) {
            float src = (j < 8) ? bp0 : bp1;
            bj[j] += __shfl_sync(0xffffffffu, src, (lane & 24) | (j & 7));
        }
    } else {
        float b0 = 0.f, b1 = 0.f;
        #pragma unroll
        for (int j = 0; j < 8; ++j)  b0 = (dq == j) ? bj[j] : b0;
        #pragma unroll
        for (int j = 8; j < 16; ++j) b1 = (dq == j - 8) ? bj[j] : b1;
        Bp[dq] = b0;
        Bp[dq + 8] = b1;
    }

    // softmax over j -> coupling coeffs into csh
    float m = bj[0];
    #pragma unroll
    for (int j = 1; j < NCAPS; ++j) m = fmaxf(m, bj[j]);
    float sum = 0.f;
    #pragma unroll
    for (int j = 0; j < NCAPS; ++j) { bj[j] = __expf(bj[j] - m); sum += bj[j]; }
    const float inv = 1.f / sum;
    {
        float c0 = 0.f, c1 = 0.f;
        #pragma unroll
        for (int j = 0; j < 8; ++j)  c0 = (dq == j) ? bj[j] : c0;
        #pragma unroll
        for (int j = 8; j < 16; ++j) c1 = (dq == j - 8) ? bj[j] : c1;
        csh[il * CSTRIDE + dq]     = c0 * inv;
        csh[il * CSTRIDE + dq + 8] = c1 * inv;
    }
    __syncthreads();

    // ---- phase B: weighted sum, thread = half2 of (j,d) ----
    const int jB = q >> 4;                     // j = 2q/32
    const uint32_t* Ub = reinterpret_cast<const uint32_t*>(
                             g_uhat + ((size_t)b * ICAPS + chunk * 32) * 512) + q;
    float2 acc = make_float2(0.f, 0.f);
    #pragma unroll 8
    for (int ii = 0; ii < 32; ++ii) {
        float cc = csh[ii * CSTRIDE + jB];
        float2 u = unpack_f16(Ub[ii * 256]);
        acc.x = fmaf(cc, u.x, acc.x);
        acc.y = fmaf(cc, u.y, acc.y);
    }
    reinterpret_cast<float2*>(
        g_part + ((size_t)chunk * B_ + b) * 512)[q] = acc;
}

// ---------------------------------------------------------------------------
extern "C" void kernel_launch(void* const* d_in, const int* in_sizes, int n_in,
                              void* d_out, int out_size) {
    const float* x = (const float*)d_in[0];
    const float* W = (const float*)d_in[1];
    float* out = (float*)d_out;

    cudaFuncSetAttribute(uhat_mma, cudaFuncAttributeMaxDynamicSharedMemorySize,
                         SMEM_BYTES);

    uhat_mma<<<ICAPS, 256, SMEM_BYTES>>>(x, W);

    s_uniform_part<<<dim3(B_, 16), 512>>>();  // r=0 partials
    squash_reduce<<<B_, 512>>>(out, 0);       // -> v
    fused_route<<<dim3(B_, 16), 256>>>(0);    // r=1
    squash_reduce<<<B_, 512>>>(out, 0);       // -> v
    fused_route<<<dim3(B_, 16), 256>>>(1);    // r=2
    squash_reduce<<<B_, 512>>>(out, 1);       // -> out
}